// round 7
// baseline (speedup 1.0000x reference)
#include <cuda_runtime.h>
#include <cuda_bf16.h>
#include <cstdint>

#define NN 50000
#define EE 500000
#define KK 3
#define DD 128
#define KD 384          // K*D
#define LOOP_ET 100     // 2R
#define NEG 0.2f
#define BN_EPS 1e-5f
#define NBLK 196        // ceil(NN/256)

// ---------------- scratch (static __device__ globals; no runtime alloc) ----------------
__device__ float g_x[(size_t)NN * KD];      // PCA output [N, K*D]
__device__ float g_out[(size_t)NN * KD];    // aggregated pre-BN
__device__ int   g_deg[NN];
__device__ int   g_off[NN + 1];
__device__ int   g_cur[NN];
__device__ int   g_edg[EE];                 // packed: src | (et<<17)
__device__ int   g_bsum[NBLK];
__device__ float g_sum[KD];
__device__ float g_sumsq[KD];
__device__ float g_a[KD];
__device__ float g_b[KD];

// ---------------- small float4 helpers ----------------
__device__ __forceinline__ float4 f4mul(float4 a, float4 b) {
    return make_float4(a.x * b.x, a.y * b.y, a.z * b.z, a.w * b.w);
}
__device__ __forceinline__ float dot4m(float4 a, float4 b) {
    return a.x * b.x + a.y * b.y + a.z * b.z + a.w * b.w;
}
__device__ __forceinline__ void f4fma(float4& acc, float4 m, float s) {
    acc.x += m.x * s; acc.y += m.y * s; acc.z += m.z * s; acc.w += m.w * s;
}
__device__ __forceinline__ float fast_tanh(float x) {
    float y;
    asm("tanh.approx.f32 %0, %1;" : "=f"(y) : "f"(x));
    return y;
}

// ---------------- bf16 split helpers ----------------
__device__ __forceinline__ void split2(float x, float y, uint32_t& h, uint32_t& l) {
    __nv_bfloat16 hx = __float2bfloat16_rn(x);
    __nv_bfloat16 hy = __float2bfloat16_rn(y);
    float rx = x - __bfloat162float(hx);
    float ry = y - __bfloat162float(hy);
    __nv_bfloat16 lx = __float2bfloat16_rn(rx);
    __nv_bfloat16 ly = __float2bfloat16_rn(ry);
    uint16_t uhx = *(uint16_t*)&hx, uhy = *(uint16_t*)&hy;
    uint16_t ulx = *(uint16_t*)&lx, uly = *(uint16_t*)&ly;
    h = (uint32_t)uhx | ((uint32_t)uhy << 16);
    l = (uint32_t)ulx | ((uint32_t)uly << 16);
}

__device__ __forceinline__ void mma16816(float* c, const uint32_t* a,
                                         uint32_t b0, uint32_t b1) {
    asm volatile(
        "mma.sync.aligned.m16n8k16.row.col.f32.bf16.bf16.f32 "
        "{%0,%1,%2,%3}, {%4,%5,%6,%7}, {%8,%9}, {%0,%1,%2,%3};"
        : "+f"(c[0]), "+f"(c[1]), "+f"(c[2]), "+f"(c[3])
        : "r"(a[0]), "r"(a[1]), "r"(a[2]), "r"(a[3]), "r"(b0), "r"(b1));
}

// ---------------- kernel: zero scratch counters ----------------
__global__ void k_zero() {
    int i = blockIdx.x * blockDim.x + threadIdx.x;
    if (i < NN) { g_deg[i] = 0; g_cur[i] = 0; }
    if (i < KD) { g_sum[i] = 0.f; g_sumsq[i] = 0.f; }
}

// ---------------- kernel: x = init_embed @ pca_w + pca_b  (bf16 3xMMA) ----------------
// __launch_bounds__(256, 2): cap regs at 128 so 2 CTAs co-reside per SM.
__global__ __launch_bounds__(256, 2) void k_gemm(const float* __restrict__ A,
                                                 const float* __restrict__ B,
                                                 const float* __restrict__ bias) {
    __shared__ uint32_t As_h[128 * 18], As_l[128 * 18];
    __shared__ uint32_t Bs_h[128 * 19], Bs_l[128 * 19];
    int tid = threadIdx.x;
    int warp = tid >> 5, lane = tid & 31;
    int g = lane >> 2, t = lane & 3;
    int wm = warp >> 1, wn = warp & 1;
    int row0 = blockIdx.x * 128;
    int col0 = blockIdx.y * 128;

    float c[2][8][4];
#pragma unroll
    for (int mi = 0; mi < 2; mi++)
#pragma unroll
        for (int ni = 0; ni < 8; ni++)
#pragma unroll
            for (int j = 0; j < 4; j++) c[mi][ni][j] = 0.f;

    int bn = tid & 127;
    int pb0 = tid >> 7;

    for (int kb = 0; kb < 4; kb++) {
#pragma unroll
        for (int s = 0; s < 4; s++) {
            int idx = tid + s * 256;
            int r = idx >> 3, c4 = idx & 7;
            int gr = row0 + r;
            float4 v = make_float4(0.f, 0.f, 0.f, 0.f);
            if (gr < NN) v = *(const float4*)&A[(size_t)gr * DD + kb * 32 + c4 * 4];
            uint32_t h0, l0, h1, l1;
            split2(v.x, v.y, h0, l0);
            split2(v.z, v.w, h1, l1);
            As_h[r * 18 + c4 * 2] = h0; As_h[r * 18 + c4 * 2 + 1] = h1;
            As_l[r * 18 + c4 * 2] = l0; As_l[r * 18 + c4 * 2 + 1] = l1;
        }
#pragma unroll
        for (int s = 0; s < 8; s++) {
            int p = pb0 + s * 2;
            int kg = kb * 32 + 2 * p;
            float b0f = B[(size_t)kg * KD + col0 + bn];
            float b1f = B[(size_t)(kg + 1) * KD + col0 + bn];
            uint32_t h, l;
            split2(b0f, b1f, h, l);
            Bs_h[bn * 19 + p] = h;
            Bs_l[bn * 19 + p] = l;
        }
        __syncthreads();

#pragma unroll
        for (int ki = 0; ki < 2; ki++) {
            int pb = ki * 8;
            uint32_t ah[2][4], al[2][4];
#pragma unroll
            for (int mi = 0; mi < 2; mi++) {
                int r0 = (wm * 32 + mi * 16 + g) * 18;
                int r1 = r0 + 8 * 18;
                ah[mi][0] = As_h[r0 + pb + t];     ah[mi][1] = As_h[r1 + pb + t];
                ah[mi][2] = As_h[r0 + pb + 4 + t]; ah[mi][3] = As_h[r1 + pb + 4 + t];
                al[mi][0] = As_l[r0 + pb + t];     al[mi][1] = As_l[r1 + pb + t];
                al[mi][2] = As_l[r0 + pb + 4 + t]; al[mi][3] = As_l[r1 + pb + 4 + t];
            }
#pragma unroll
            for (int ni = 0; ni < 8; ni++) {
                int n = (wn * 64 + ni * 8 + g) * 19;
                uint32_t bh0 = Bs_h[n + pb + t], bh1 = Bs_h[n + pb + 4 + t];
                uint32_t bl0 = Bs_l[n + pb + t], bl1 = Bs_l[n + pb + 4 + t];
#pragma unroll
                for (int mi = 0; mi < 2; mi++) {
                    mma16816(c[mi][ni], ah[mi], bh0, bh1);   // hi*hi
                    mma16816(c[mi][ni], ah[mi], bl0, bl1);   // hi*lo
                    mma16816(c[mi][ni], al[mi], bh0, bh1);   // lo*hi
                }
            }
        }
        __syncthreads();
    }

#pragma unroll
    for (int mi = 0; mi < 2; mi++) {
        int row = row0 + wm * 32 + mi * 16 + g;
#pragma unroll
        for (int ni = 0; ni < 8; ni++) {
            int col = col0 + wn * 64 + ni * 8 + 2 * t;
            float bx = __ldg(&bias[col]), by = __ldg(&bias[col + 1]);
            if (row < NN) {
                float2 v0 = make_float2(c[mi][ni][0] + bx, c[mi][ni][1] + by);
                *(float2*)&g_x[(size_t)row * KD + col] = v0;
            }
            if (row + 8 < NN) {
                float2 v1 = make_float2(c[mi][ni][2] + bx, c[mi][ni][3] + by);
                *(float2*)&g_x[(size_t)(row + 8) * KD + col] = v1;
            }
        }
    }
}

// ---------------- kernel: degree histogram over dst ----------------
__global__ void k_hist(const int* __restrict__ ei) {
    int e = blockIdx.x * blockDim.x + threadIdx.x;
    if (e < EE) atomicAdd(&g_deg[ei[EE + e]], 1);
}

// ---------------- scan ----------------
__device__ __forceinline__ int block_scan_256(int v, int* wsum) {
    int lane = threadIdx.x & 31, wid = threadIdx.x >> 5;
    int x = v;
#pragma unroll
    for (int s = 1; s < 32; s <<= 1) {
        int y = __shfl_up_sync(0xffffffffu, x, s);
        if (lane >= s) x += y;
    }
    if (lane == 31) wsum[wid] = x;
    __syncthreads();
    if (wid == 0) {
        int y = (lane < 8) ? wsum[lane] : 0;
#pragma unroll
        for (int s = 1; s < 8; s <<= 1) {
            int z = __shfl_up_sync(0xffffffffu, y, s);
            if (lane >= s) y += z;
        }
        if (lane < 8) wsum[lane] = y;
    }
    __syncthreads();
    return x + (wid > 0 ? wsum[wid - 1] : 0);   // inclusive
}

__global__ void k_scanA() {   // per-block sums
    __shared__ int wsum[8];
    int i = blockIdx.x * 256 + threadIdx.x;
    int v = (i < NN) ? g_deg[i] : 0;
    int incl = block_scan_256(v, wsum);
    if (threadIdx.x == 255) g_bsum[blockIdx.x] = incl;
}

// final offsets; each block computes its own prefix over g_bsum (196 ints)
__global__ void k_scanC() {
    __shared__ int wsum[8];
    __shared__ int s_pre;
    int t = threadIdx.x, lane = t & 31, wid = t >> 5;

    int acc = 0;
    for (int i = t; i < blockIdx.x; i += 256) acc += g_bsum[i];
#pragma unroll
    for (int s = 16; s; s >>= 1) acc += __shfl_xor_sync(0xffffffffu, acc, s);
    if (lane == 0) wsum[wid] = acc;
    __syncthreads();
    if (t == 0) {
        int tot = 0;
#pragma unroll
        for (int w = 0; w < 8; w++) tot += wsum[w];
        s_pre = tot;
    }
    __syncthreads();
    int pre = s_pre;
    __syncthreads();     // wsum reused by block_scan below

    int i = blockIdx.x * 256 + t;
    int v = (i < NN) ? g_deg[i] : 0;
    int incl = block_scan_256(v, wsum);
    if (i < NN) g_off[i + 1] = incl + pre;
    if (i == 0) g_off[0] = 0;
}

// ---------------- kernel: scatter edges into CSR ----------------
__global__ void k_scatter(const int* __restrict__ ei, const int* __restrict__ et) {
    int e = blockIdx.x * blockDim.x + threadIdx.x;
    if (e < EE) {
        int dst = ei[EE + e];
        int pos = g_off[dst] + atomicAdd(&g_cur[dst], 1);
        g_edg[pos] = ei[e] | (et[e] << 17);
    }
}

// ---------------- per-edge, per-factor aggregation step ----------------
__device__ __forceinline__ void agg_one_k(
    float4 xi, float4 xj, int et, int k, int lane,
    const float* __restrict__ init_rel, const float* __restrict__ loop_rel,
    const float* __restrict__ rel_weight,
    float4& acc, float& den)
{
    const float4* w4 = (const float4*)(rel_weight + (size_t)et * KD + k * DD);
    const float4* r4 = (const float4*)((et < LOOP_ET) ? (init_rel + (size_t)et * DD)
                                                      : loop_rel);
    float4 w = __ldg(w4 + lane);
    float4 r = __ldg(r4 + lane);

    float4 jw = f4mul(xj, w);
    float p = dot4m(f4mul(xi, w), jw);
#pragma unroll
    for (int s = 16; s; s >>= 1) p += __shfl_xor_sync(0xffffffffu, p, s);

    float a = p > 0.f ? p : NEG * p;
    float e = __expf(a);
    den += e;

    float4 rp = make_float4(r.x + 1.f, r.y + 1.f, r.z + 1.f, r.w + 1.f);
    f4fma(acc, f4mul(jw, rp), e);
}

// ---------------- kernel: aggregation, 3 warps per node (one per factor) ----------------
// blockDim=384 (12 warps = 4 nodes x 3 factors). Prefetch next edge's x_j slice.
__global__ __launch_bounds__(384) void k_agg(const float* __restrict__ init_rel,
                                             const float* __restrict__ loop_rel,
                                             const float* __restrict__ rel_weight) {
    int wid = threadIdx.x >> 5;
    int lane = threadIdx.x & 31;
    int nl = wid / 3;                    // node-local 0..3
    int k = wid - 3 * nl;                // factor 0..2
    int node = blockIdx.x * 4 + nl;
    if (node >= NN) return;

    const float4* xrow = (const float4*)(g_x + (size_t)node * KD + k * DD);
    float4 xi = __ldcg(xrow + lane);

    float4 acc = make_float4(0, 0, 0, 0);
    float den = 0.f;

    // self-loop (no gather)
    agg_one_k(xi, xi, LOOP_ET, k, lane, init_rel, loop_rel, rel_weight, acc, den);

    int beg = g_off[node], end = g_off[node + 1];
    if (beg < end) {
        int p0 = g_edg[beg];
        int net = p0 >> 17;
        float4 nx = __ldcg((const float4*)(g_x + (size_t)(p0 & 0x1FFFF) * KD + k * DD) + lane);

        for (int e = beg; e < end; e++) {
            float4 xj = nx;
            int et = net;
            if (e + 1 < end) {
                int p1 = g_edg[e + 1];
                net = p1 >> 17;
                nx = __ldcg((const float4*)(g_x + (size_t)(p1 & 0x1FFFF) * KD + k * DD) + lane);
            }
            agg_one_k(xi, xj, et, k, lane, init_rel, loop_rel, rel_weight, acc, den);
        }
    }

    float inv = 1.f / (den + 1e-16f);
    float4* orow = (float4*)(g_out + (size_t)node * KD + k * DD);
    orow[lane] = make_float4(acc.x * inv, acc.y * inv, acc.z * inv, acc.w * inv);
}

// ---------------- kernel: BN column stats ----------------
__global__ void k_bnstats() {
    int col = threadIdx.x;   // blockDim = 384
    float s = 0.f, s2 = 0.f;
    for (int row = blockIdx.x; row < NN; row += gridDim.x) {
        float v = g_out[(size_t)row * KD + col];
        s += v; s2 += v * v;
    }
    atomicAdd(&g_sum[col], s);
    atomicAdd(&g_sumsq[col], s2);
}

// ---------------- kernel: finalize BN coefficients ----------------
__global__ void k_bnfinal(const float* __restrict__ gamma, const float* __restrict__ beta) {
    int c = threadIdx.x;
    if (c < KD) {
        float mu = g_sum[c] / (float)NN;
        float var = g_sumsq[c] / (float)NN - mu * mu;
        float a = gamma[c] * rsqrtf(var + BN_EPS);
        g_a[c] = a;
        g_b[c] = beta[c] - mu * a;
    }
}

// ---------------- kernel: normalize + tanh -> d_out ----------------
__global__ void k_apply(float* __restrict__ out) {
    int i = blockIdx.x * blockDim.x + threadIdx.x;   // float4 index
    if (i < NN * (KD / 4)) {
        int c4 = (i % (KD / 4)) * 4;
        float4 v = *(const float4*)&g_out[(size_t)i * 4];
        float4 y;
        y.x = fast_tanh(v.x * g_a[c4 + 0] + g_b[c4 + 0]);
        y.y = fast_tanh(v.y * g_a[c4 + 1] + g_b[c4 + 1]);
        y.z = fast_tanh(v.z * g_a[c4 + 2] + g_b[c4 + 2]);
        y.w = fast_tanh(v.w * g_a[c4 + 3] + g_b[c4 + 3]);
        ((float4*)out)[i] = y;
    }
}

// ---------------- launch ----------------
extern "C" void kernel_launch(void* const* d_in, const int* in_sizes, int n_in,
                              void* d_out, int out_size) {
    const float* init_embed = (const float*)d_in[0];
    const float* init_rel   = (const float*)d_in[1];
    const float* pca_w      = (const float*)d_in[2];
    const float* pca_b      = (const float*)d_in[3];
    const float* loop_rel   = (const float*)d_in[4];
    const float* rel_weight = (const float*)d_in[5];
    const float* bn_gamma   = (const float*)d_in[6];
    const float* bn_beta    = (const float*)d_in[7];
    const int*   edge_index = (const int*)d_in[8];
    const int*   edge_type  = (const int*)d_in[9];
    float* out = (float*)d_out;

    k_zero<<<(NN + 255) / 256, 256>>>();                         // 1
    k_hist<<<(EE + 255) / 256, 256>>>(edge_index);               // 2
    k_scanA<<<NBLK, 256>>>();                                    // 3

    dim3 gg((NN + 127) / 128, KD / 128);
    k_gemm<<<gg, 256>>>(init_embed, pca_w, pca_b);               // 4 <- ncu capture

    k_scanC<<<NBLK, 256>>>();                                    // 5
    k_scatter<<<(EE + 255) / 256, 256>>>(edge_index, edge_type); // 6

    k_agg<<<(NN + 3) / 4, 384>>>(init_rel, loop_rel, rel_weight);

    k_bnstats<<<512, 384>>>();
    k_bnfinal<<<1, 384>>>(bn_gamma, bn_beta);
    k_apply<<<(NN * (KD / 4) + 255) / 256, 256>>>(out);
}

// round 8
// speedup vs baseline: 1.0054x; 1.0054x over previous
#include <cuda_runtime.h>
#include <cuda_bf16.h>
#include <cstdint>

#define NN 50000
#define EE 500000
#define KK 3
#define DD 128
#define KD 384          // K*D
#define LOOP_ET 100     // 2R
#define NEG 0.2f
#define BN_EPS 1e-5f
#define NBLK 196        // ceil(NN/256)

// ---------------- scratch (static __device__ globals; no runtime alloc) ----------------
__device__ float g_x[(size_t)NN * KD];      // PCA output [N, K*D]
__device__ float g_out[(size_t)NN * KD];    // aggregated pre-BN
__device__ int   g_deg[NN];
__device__ int   g_off[NN + 1];
__device__ int   g_cur[NN];
__device__ int   g_edg[EE];                 // packed: src | (et<<17)
__device__ int   g_bsum[NBLK];
__device__ float g_sum[KD];
__device__ float g_sumsq[KD];
__device__ float g_a[KD];
__device__ float g_b[KD];

// ---------------- small float4 helpers ----------------
__device__ __forceinline__ float4 f4mul(float4 a, float4 b) {
    return make_float4(a.x * b.x, a.y * b.y, a.z * b.z, a.w * b.w);
}
__device__ __forceinline__ float dot4m(float4 a, float4 b) {
    return a.x * b.x + a.y * b.y + a.z * b.z + a.w * b.w;
}
__device__ __forceinline__ void f4fma(float4& acc, float4 m, float s) {
    acc.x += m.x * s; acc.y += m.y * s; acc.z += m.z * s; acc.w += m.w * s;
}
__device__ __forceinline__ float fast_tanh(float x) {
    float y;
    asm("tanh.approx.f32 %0, %1;" : "=f"(y) : "f"(x));
    return y;
}

// ---------------- bf16 split helpers ----------------
__device__ __forceinline__ void split2(float x, float y, uint32_t& h, uint32_t& l) {
    __nv_bfloat16 hx = __float2bfloat16_rn(x);
    __nv_bfloat16 hy = __float2bfloat16_rn(y);
    float rx = x - __bfloat162float(hx);
    float ry = y - __bfloat162float(hy);
    __nv_bfloat16 lx = __float2bfloat16_rn(rx);
    __nv_bfloat16 ly = __float2bfloat16_rn(ry);
    uint16_t uhx = *(uint16_t*)&hx, uhy = *(uint16_t*)&hy;
    uint16_t ulx = *(uint16_t*)&lx, uly = *(uint16_t*)&ly;
    h = (uint32_t)uhx | ((uint32_t)uhy << 16);
    l = (uint32_t)ulx | ((uint32_t)uly << 16);
}

__device__ __forceinline__ void mma16816(float* c, const uint32_t* a,
                                         uint32_t b0, uint32_t b1) {
    asm volatile(
        "mma.sync.aligned.m16n8k16.row.col.f32.bf16.bf16.f32 "
        "{%0,%1,%2,%3}, {%4,%5,%6,%7}, {%8,%9}, {%0,%1,%2,%3};"
        : "+f"(c[0]), "+f"(c[1]), "+f"(c[2]), "+f"(c[3])
        : "r"(a[0]), "r"(a[1]), "r"(a[2]), "r"(a[3]), "r"(b0), "r"(b1));
}

// ---------------- kernel: zero scratch counters ----------------
__global__ void k_zero() {
    int i = blockIdx.x * blockDim.x + threadIdx.x;
    if (i < NN) { g_deg[i] = 0; g_cur[i] = 0; }
    if (i < KD) { g_sum[i] = 0.f; g_sumsq[i] = 0.f; }
}

// ---------------- kernel: x = init_embed @ pca_w + pca_b  (bf16 3xMMA) ----------------
__global__ __launch_bounds__(256, 2) void k_gemm(const float* __restrict__ A,
                                                 const float* __restrict__ B,
                                                 const float* __restrict__ bias) {
    __shared__ uint32_t As_h[128 * 18], As_l[128 * 18];
    __shared__ uint32_t Bs_h[128 * 19], Bs_l[128 * 19];
    int tid = threadIdx.x;
    int warp = tid >> 5, lane = tid & 31;
    int g = lane >> 2, t = lane & 3;
    int wm = warp >> 1, wn = warp & 1;
    int row0 = blockIdx.x * 128;
    int col0 = blockIdx.y * 128;

    float c[2][8][4];
#pragma unroll
    for (int mi = 0; mi < 2; mi++)
#pragma unroll
        for (int ni = 0; ni < 8; ni++)
#pragma unroll
            for (int j = 0; j < 4; j++) c[mi][ni][j] = 0.f;

    int bn = tid & 127;
    int pb0 = tid >> 7;

    for (int kb = 0; kb < 4; kb++) {
#pragma unroll
        for (int s = 0; s < 4; s++) {
            int idx = tid + s * 256;
            int r = idx >> 3, c4 = idx & 7;
            int gr = row0 + r;
            float4 v = make_float4(0.f, 0.f, 0.f, 0.f);
            if (gr < NN) v = *(const float4*)&A[(size_t)gr * DD + kb * 32 + c4 * 4];
            uint32_t h0, l0, h1, l1;
            split2(v.x, v.y, h0, l0);
            split2(v.z, v.w, h1, l1);
            As_h[r * 18 + c4 * 2] = h0; As_h[r * 18 + c4 * 2 + 1] = h1;
            As_l[r * 18 + c4 * 2] = l0; As_l[r * 18 + c4 * 2 + 1] = l1;
        }
#pragma unroll
        for (int s = 0; s < 8; s++) {
            int p = pb0 + s * 2;
            int kg = kb * 32 + 2 * p;
            float b0f = B[(size_t)kg * KD + col0 + bn];
            float b1f = B[(size_t)(kg + 1) * KD + col0 + bn];
            uint32_t h, l;
            split2(b0f, b1f, h, l);
            Bs_h[bn * 19 + p] = h;
            Bs_l[bn * 19 + p] = l;
        }
        __syncthreads();

#pragma unroll
        for (int ki = 0; ki < 2; ki++) {
            int pb = ki * 8;
            uint32_t ah[2][4], al[2][4];
#pragma unroll
            for (int mi = 0; mi < 2; mi++) {
                int r0 = (wm * 32 + mi * 16 + g) * 18;
                int r1 = r0 + 8 * 18;
                ah[mi][0] = As_h[r0 + pb + t];     ah[mi][1] = As_h[r1 + pb + t];
                ah[mi][2] = As_h[r0 + pb + 4 + t]; ah[mi][3] = As_h[r1 + pb + 4 + t];
                al[mi][0] = As_l[r0 + pb + t];     al[mi][1] = As_l[r1 + pb + t];
                al[mi][2] = As_l[r0 + pb + 4 + t]; al[mi][3] = As_l[r1 + pb + 4 + t];
            }
#pragma unroll
            for (int ni = 0; ni < 8; ni++) {
                int n = (wn * 64 + ni * 8 + g) * 19;
                uint32_t bh0 = Bs_h[n + pb + t], bh1 = Bs_h[n + pb + 4 + t];
                uint32_t bl0 = Bs_l[n + pb + t], bl1 = Bs_l[n + pb + 4 + t];
#pragma unroll
                for (int mi = 0; mi < 2; mi++) {
                    mma16816(c[mi][ni], ah[mi], bh0, bh1);   // hi*hi
                    mma16816(c[mi][ni], ah[mi], bl0, bl1);   // hi*lo
                    mma16816(c[mi][ni], al[mi], bh0, bh1);   // lo*hi
                }
            }
        }
        __syncthreads();
    }

#pragma unroll
    for (int mi = 0; mi < 2; mi++) {
        int row = row0 + wm * 32 + mi * 16 + g;
#pragma unroll
        for (int ni = 0; ni < 8; ni++) {
            int col = col0 + wn * 64 + ni * 8 + 2 * t;
            float bx = __ldg(&bias[col]), by = __ldg(&bias[col + 1]);
            if (row < NN) {
                float2 v0 = make_float2(c[mi][ni][0] + bx, c[mi][ni][1] + by);
                *(float2*)&g_x[(size_t)row * KD + col] = v0;
            }
            if (row + 8 < NN) {
                float2 v1 = make_float2(c[mi][ni][2] + bx, c[mi][ni][3] + by);
                *(float2*)&g_x[(size_t)(row + 8) * KD + col] = v1;
            }
        }
    }
}

// ---------------- kernel: degree histogram over dst ----------------
__global__ void k_hist(const int* __restrict__ ei) {
    int e = blockIdx.x * blockDim.x + threadIdx.x;
    if (e < EE) atomicAdd(&g_deg[ei[EE + e]], 1);
}

// ---------------- scan ----------------
__device__ __forceinline__ int block_scan_256(int v, int* wsum) {
    int lane = threadIdx.x & 31, wid = threadIdx.x >> 5;
    int x = v;
#pragma unroll
    for (int s = 1; s < 32; s <<= 1) {
        int y = __shfl_up_sync(0xffffffffu, x, s);
        if (lane >= s) x += y;
    }
    if (lane == 31) wsum[wid] = x;
    __syncthreads();
    if (wid == 0) {
        int y = (lane < 8) ? wsum[lane] : 0;
#pragma unroll
        for (int s = 1; s < 8; s <<= 1) {
            int z = __shfl_up_sync(0xffffffffu, y, s);
            if (lane >= s) y += z;
        }
        if (lane < 8) wsum[lane] = y;
    }
    __syncthreads();
    return x + (wid > 0 ? wsum[wid - 1] : 0);   // inclusive
}

__global__ void k_scanA() {   // per-block sums
    __shared__ int wsum[8];
    int i = blockIdx.x * 256 + threadIdx.x;
    int v = (i < NN) ? g_deg[i] : 0;
    int incl = block_scan_256(v, wsum);
    if (threadIdx.x == 255) g_bsum[blockIdx.x] = incl;
}

__global__ void k_scanC() {   // final offsets
    __shared__ int wsum[8];
    __shared__ int s_pre;
    int t = threadIdx.x, lane = t & 31, wid = t >> 5;

    int acc = 0;
    for (int i = t; i < blockIdx.x; i += 256) acc += g_bsum[i];
#pragma unroll
    for (int s = 16; s; s >>= 1) acc += __shfl_xor_sync(0xffffffffu, acc, s);
    if (lane == 0) wsum[wid] = acc;
    __syncthreads();
    if (t == 0) {
        int tot = 0;
#pragma unroll
        for (int w = 0; w < 8; w++) tot += wsum[w];
        s_pre = tot;
    }
    __syncthreads();
    int pre = s_pre;
    __syncthreads();

    int i = blockIdx.x * 256 + t;
    int v = (i < NN) ? g_deg[i] : 0;
    int incl = block_scan_256(v, wsum);
    if (i < NN) g_off[i + 1] = incl + pre;
    if (i == 0) g_off[0] = 0;
}

// ---------------- kernel: scatter edges into CSR ----------------
__global__ void k_scatter(const int* __restrict__ ei, const int* __restrict__ et) {
    int e = blockIdx.x * blockDim.x + threadIdx.x;
    if (e < EE) {
        int dst = ei[EE + e];
        int pos = g_off[dst] + atomicAdd(&g_cur[dst], 1);
        g_edg[pos] = ei[e] | (et[e] << 17);
    }
}

// ---------------- aggregation: per-edge step (all 3 factors) ----------------
__device__ __forceinline__ void agg_one(
    float4 xi0, float4 xi1, float4 xi2,
    float4 xj0, float4 xj1, float4 xj2,
    int et, int lane,
    const float* __restrict__ init_rel, const float* __restrict__ loop_rel,
    const float* __restrict__ rel_weight,
    float4& acc0, float4& acc1, float4& acc2,
    float& den0, float& den1, float& den2)
{
    const float4* w4 = (const float4*)(rel_weight + (size_t)et * (KK * DD));
    const float4* r4 = (const float4*)((et < LOOP_ET) ? (init_rel + (size_t)et * DD)
                                                      : loop_rel);
    float4 r  = __ldg(r4 + lane);
    float4 w0 = __ldg(w4 + lane);
    float4 w1 = __ldg(w4 + 32 + lane);
    float4 w2 = __ldg(w4 + 64 + lane);

    float4 jw0 = f4mul(xj0, w0);
    float4 jw1 = f4mul(xj1, w1);
    float4 jw2 = f4mul(xj2, w2);

    float p0 = dot4m(f4mul(xi0, w0), jw0);
    float p1 = dot4m(f4mul(xi1, w1), jw1);
    float p2 = dot4m(f4mul(xi2, w2), jw2);
#pragma unroll
    for (int s = 16; s; s >>= 1) {
        p0 += __shfl_xor_sync(0xffffffffu, p0, s);
        p1 += __shfl_xor_sync(0xffffffffu, p1, s);
        p2 += __shfl_xor_sync(0xffffffffu, p2, s);
    }
    float a0 = p0 > 0.f ? p0 : NEG * p0;
    float a1 = p1 > 0.f ? p1 : NEG * p1;
    float a2 = p2 > 0.f ? p2 : NEG * p2;
    float e0 = __expf(a0), e1 = __expf(a1), e2 = __expf(a2);
    den0 += e0; den1 += e1; den2 += e2;

    float4 rp = make_float4(r.x + 1.f, r.y + 1.f, r.z + 1.f, r.w + 1.f);
    f4fma(acc0, f4mul(jw0, rp), e0);
    f4fma(acc1, f4mul(jw1, rp), e1);
    f4fma(acc2, f4mul(jw2, rp), e2);
}

// slot load: gathers one edge's x_j (3x LDG.128) + type; predicated
#define LOADSLOT(S, idx) do {                                                 \
    if ((idx) < end) {                                                        \
        int pp = g_edg[(idx)];                                                \
        S##et = pp >> 17;                                                     \
        const float4* xs = (const float4*)(g_x + (size_t)(pp & 0x1FFFF) * KD);\
        S##x0 = __ldcg(xs + lane);                                            \
        S##x1 = __ldcg(xs + 32 + lane);                                       \
        S##x2 = __ldcg(xs + 64 + lane);                                       \
    }                                                                         \
} while (0)

#define PROCSLOT(S)                                                           \
    agg_one(xi0, xi1, xi2, S##x0, S##x1, S##x2, S##et, lane,                  \
            init_rel, loop_rel, rel_weight, acc0, acc1, acc2, den0, den1, den2)

// ---------------- kernel: aggregation, 1 warp/node, 4-deep edge pipeline ----------------
__global__ __launch_bounds__(256, 2) void k_agg(const float* __restrict__ init_rel,
                                                const float* __restrict__ loop_rel,
                                                const float* __restrict__ rel_weight) {
    int warp = (blockIdx.x * 256 + threadIdx.x) >> 5;
    int lane = threadIdx.x & 31;
    if (warp >= NN) return;
    int node = warp;

    const float4* xrow = (const float4*)(g_x + (size_t)node * KD);
    float4 xi0 = __ldcg(xrow + lane);
    float4 xi1 = __ldcg(xrow + 32 + lane);
    float4 xi2 = __ldcg(xrow + 64 + lane);

    float4 acc0 = make_float4(0, 0, 0, 0);
    float4 acc1 = make_float4(0, 0, 0, 0);
    float4 acc2 = make_float4(0, 0, 0, 0);
    float den0 = 0.f, den1 = 0.f, den2 = 0.f;

    int beg = g_off[node], end = g_off[node + 1];

    // 4 pipeline slots (named registers; no dynamic indexing)
    float4 ax0, ax1, ax2; int aet;
    float4 bx0, bx1, bx2; int bet;
    float4 cx0, cx1, cx2; int cet;
    float4 dx0, dx1, dx2; int det;

    LOADSLOT(a, beg + 0);
    LOADSLOT(b, beg + 1);
    LOADSLOT(c, beg + 2);
    LOADSLOT(d, beg + 3);

    // self-loop while the first gathers are in flight
    agg_one(xi0, xi1, xi2, xi0, xi1, xi2, LOOP_ET, lane,
            init_rel, loop_rel, rel_weight, acc0, acc1, acc2, den0, den1, den2);

    for (int e = beg; e < end; e += 4) {
        { PROCSLOT(a); LOADSLOT(a, e + 4); }
        if (e + 1 < end) { PROCSLOT(b); LOADSLOT(b, e + 5); }
        if (e + 2 < end) { PROCSLOT(c); LOADSLOT(c, e + 6); }
        if (e + 3 < end) { PROCSLOT(d); LOADSLOT(d, e + 7); }
    }

    float i0 = 1.f / (den0 + 1e-16f);
    float i1 = 1.f / (den1 + 1e-16f);
    float i2 = 1.f / (den2 + 1e-16f);
    float4* orow = (float4*)(g_out + (size_t)node * KD);
    orow[lane]      = make_float4(acc0.x * i0, acc0.y * i0, acc0.z * i0, acc0.w * i0);
    orow[32 + lane] = make_float4(acc1.x * i1, acc1.y * i1, acc1.z * i1, acc1.w * i1);
    orow[64 + lane] = make_float4(acc2.x * i2, acc2.y * i2, acc2.z * i2, acc2.w * i2);
}

// ---------------- kernel: BN column stats ----------------
__global__ void k_bnstats() {
    int col = threadIdx.x;   // blockDim = 384
    float s = 0.f, s2 = 0.f;
    for (int row = blockIdx.x; row < NN; row += gridDim.x) {
        float v = g_out[(size_t)row * KD + col];
        s += v; s2 += v * v;
    }
    atomicAdd(&g_sum[col], s);
    atomicAdd(&g_sumsq[col], s2);
}

// ---------------- kernel: finalize BN coefficients ----------------
__global__ void k_bnfinal(const float* __restrict__ gamma, const float* __restrict__ beta) {
    int c = threadIdx.x;
    if (c < KD) {
        float mu = g_sum[c] / (float)NN;
        float var = g_sumsq[c] / (float)NN - mu * mu;
        float a = gamma[c] * rsqrtf(var + BN_EPS);
        g_a[c] = a;
        g_b[c] = beta[c] - mu * a;
    }
}

// ---------------- kernel: normalize + tanh -> d_out ----------------
__global__ void k_apply(float* __restrict__ out) {
    int i = blockIdx.x * blockDim.x + threadIdx.x;   // float4 index
    if (i < NN * (KD / 4)) {
        int c4 = (i % (KD / 4)) * 4;
        float4 v = *(const float4*)&g_out[(size_t)i * 4];
        float4 y;
        y.x = fast_tanh(v.x * g_a[c4 + 0] + g_b[c4 + 0]);
        y.y = fast_tanh(v.y * g_a[c4 + 1] + g_b[c4 + 1]);
        y.z = fast_tanh(v.z * g_a[c4 + 2] + g_b[c4 + 2]);
        y.w = fast_tanh(v.w * g_a[c4 + 3] + g_b[c4 + 3]);
        ((float4*)out)[i] = y;
    }
}

// ---------------- launch ----------------
extern "C" void kernel_launch(void* const* d_in, const int* in_sizes, int n_in,
                              void* d_out, int out_size) {
    const float* init_embed = (const float*)d_in[0];
    const float* init_rel   = (const float*)d_in[1];
    const float* pca_w      = (const float*)d_in[2];
    const float* pca_b      = (const float*)d_in[3];
    const float* loop_rel   = (const float*)d_in[4];
    const float* rel_weight = (const float*)d_in[5];
    const float* bn_gamma   = (const float*)d_in[6];
    const float* bn_beta    = (const float*)d_in[7];
    const int*   edge_index = (const int*)d_in[8];
    const int*   edge_type  = (const int*)d_in[9];
    float* out = (float*)d_out;

    k_zero<<<(NN + 255) / 256, 256>>>();                         // 1
    k_hist<<<(EE + 255) / 256, 256>>>(edge_index);               // 2
    k_scanA<<<NBLK, 256>>>();                                    // 3

    dim3 gg((NN + 127) / 128, KD / 128);
    k_gemm<<<gg, 256>>>(init_embed, pca_w, pca_b);               // 4 <- ncu capture

    k_scanC<<<NBLK, 256>>>();                                    // 5
    k_scatter<<<(EE + 255) / 256, 256>>>(edge_index, edge_type); // 6

    k_agg<<<(NN * 32 + 255) / 256, 256>>>(init_rel, loop_rel, rel_weight);

    k_bnstats<<<512, 384>>>();
    k_bnfinal<<<1, 384>>>(bn_gamma, bn_beta);
    k_apply<<<(NN * (KD / 4) + 255) / 256, 256>>>(out);
}

// round 10
// speedup vs baseline: 1.0850x; 1.0792x over previous
#include <cuda_runtime.h>
#include <cuda_bf16.h>
#include <cuda_fp16.h>
#include <cstdint>

#define NN 50000
#define EE 500000
#define KK 3
#define DD 128
#define KD 384          // K*D
#define LOOP_ET 100     // 2R
#define NEG 0.2f
#define BN_EPS 1e-5f
#define NBLK 196        // ceil(NN/256)

// ---------------- scratch (static __device__ globals; no runtime alloc) ----------------
__device__ float    g_x[(size_t)NN * KD];     // PCA output fp32 [N, K*D]
__device__ uint32_t g_xh[(size_t)NN * (KD/2)];// PCA output fp16x2 [N, K*D/2]
__device__ float    g_out[(size_t)NN * KD];   // aggregated pre-BN
__device__ uint32_t g_ah[(size_t)NN * 64];    // A hi bf16 pairs [N][64]
__device__ uint32_t g_al[(size_t)NN * 64];    // A lo
__device__ uint32_t g_bh[(size_t)KD * 64];    // B hi, transposed [n][kpair]
__device__ uint32_t g_bl[(size_t)KD * 64];    // B lo
__device__ int   g_deg[NN];
__device__ int   g_off[NN + 1];
__device__ int   g_cur[NN];
__device__ int   g_edg[EE];                   // packed: src | (et<<17)
__device__ int   g_bsum[NBLK];
__device__ float g_sum[KD];
__device__ float g_sumsq[KD];
__device__ float g_a[KD];
__device__ float g_b[KD];

// ---------------- small float4 helpers ----------------
__device__ __forceinline__ float4 f4mul(float4 a, float4 b) {
    return make_float4(a.x * b.x, a.y * b.y, a.z * b.z, a.w * b.w);
}
__device__ __forceinline__ float dot4m(float4 a, float4 b) {
    return a.x * b.x + a.y * b.y + a.z * b.z + a.w * b.w;
}
__device__ __forceinline__ void f4fma(float4& acc, float4 m, float s) {
    acc.x += m.x * s; acc.y += m.y * s; acc.z += m.z * s; acc.w += m.w * s;
}
__device__ __forceinline__ float fast_tanh(float x) {
    float y;
    asm("tanh.approx.f32 %0, %1;" : "=f"(y) : "f"(x));
    return y;
}
__device__ __forceinline__ float4 h2x4(uint2 u) {
    float2 a = __half22float2(*reinterpret_cast<__half2*>(&u.x));
    float2 b = __half22float2(*reinterpret_cast<__half2*>(&u.y));
    return make_float4(a.x, a.y, b.x, b.y);
}

// ---------------- bf16 split helpers (GEMM inputs) ----------------
__device__ __forceinline__ void split2(float x, float y, uint32_t& h, uint32_t& l) {
    __nv_bfloat16 hx = __float2bfloat16_rn(x);
    __nv_bfloat16 hy = __float2bfloat16_rn(y);
    float rx = x - __bfloat162float(hx);
    float ry = y - __bfloat162float(hy);
    __nv_bfloat16 lx = __float2bfloat16_rn(rx);
    __nv_bfloat16 ly = __float2bfloat16_rn(ry);
    uint16_t uhx = *(uint16_t*)&hx, uhy = *(uint16_t*)&hy;
    uint16_t ulx = *(uint16_t*)&lx, uly = *(uint16_t*)&ly;
    h = (uint32_t)uhx | ((uint32_t)uhy << 16);
    l = (uint32_t)ulx | ((uint32_t)uly << 16);
}

__device__ __forceinline__ void mma16816(float* c, const uint32_t* a,
                                         uint32_t b0, uint32_t b1) {
    asm volatile(
        "mma.sync.aligned.m16n8k16.row.col.f32.bf16.bf16.f32 "
        "{%0,%1,%2,%3}, {%4,%5,%6,%7}, {%8,%9}, {%0,%1,%2,%3};"
        : "+f"(c[0]), "+f"(c[1]), "+f"(c[2]), "+f"(c[3])
        : "r"(a[0]), "r"(a[1]), "r"(a[2]), "r"(a[3]), "r"(b0), "r"(b1));
}

// ---------------- kernel: zero scratch counters ----------------
__global__ void k_zero() {
    int i = blockIdx.x * blockDim.x + threadIdx.x;
    if (i < NN) { g_deg[i] = 0; g_cur[i] = 0; }
    if (i < KD) { g_sum[i] = 0.f; g_sumsq[i] = 0.f; }
}

// ---------------- kernel: pre-split A and B into bf16 hi/lo ----------------
#define NA_PAIRS (NN * 64)
#define NB_PAIRS (KD * 64)
__global__ void k_split(const float* __restrict__ A, const float* __restrict__ B) {
    int i = blockIdx.x * blockDim.x + threadIdx.x;
    if (i < NA_PAIRS) {
        float2 v = *(const float2*)&A[(size_t)i * 2];
        uint32_t h, l;
        split2(v.x, v.y, h, l);
        g_ah[i] = h; g_al[i] = l;
    } else if (i < NA_PAIRS + NB_PAIRS) {
        int j = i - NA_PAIRS;          // j = n*64 + p
        int n = j >> 6, p = j & 63;
        float b0 = B[(size_t)(2 * p) * KD + n];
        float b1 = B[(size_t)(2 * p + 1) * KD + n];
        uint32_t h, l;
        split2(b0, b1, h, l);
        g_bh[j] = h; g_bl[j] = l;
    }
}

// ---------------- kernel: x = init_embed @ pca_w + pca_b  (bf16 3xMMA) ----------------
// pre-split inputs; staging is pure LDG/STS. Also writes fp16 copy g_xh.
__global__ __launch_bounds__(256, 2) void k_gemm(const float* __restrict__ bias) {
    __shared__ uint32_t As_h[128 * 18], As_l[128 * 18];
    __shared__ uint32_t Bs_h[128 * 19], Bs_l[128 * 19];
    int tid = threadIdx.x;
    int warp = tid >> 5, lane = tid & 31;
    int g = lane >> 2, t = lane & 3;
    int wm = warp >> 1, wn = warp & 1;
    int row0 = blockIdx.x * 128;
    int col0 = blockIdx.y * 128;

    float c[2][8][4];
#pragma unroll
    for (int mi = 0; mi < 2; mi++)
#pragma unroll
        for (int ni = 0; ni < 8; ni++)
#pragma unroll
            for (int j = 0; j < 4; j++) c[mi][ni][j] = 0.f;

    for (int kb = 0; kb < 4; kb++) {
        // A tile: 128 rows x 16 kpairs (hi + lo)
#pragma unroll
        for (int s = 0; s < 8; s++) {
            int idx = tid + s * 256;
            int r = idx >> 4, p = idx & 15;
            int gr = row0 + r;
            uint32_t h = 0, l = 0;
            if (gr < NN) {
                size_t o = (size_t)gr * 64 + kb * 16 + p;
                h = g_ah[o]; l = g_al[o];
            }
            As_h[r * 18 + p] = h;
            As_l[r * 18 + p] = l;
        }
        // B tile: 128 n x 16 kpairs
#pragma unroll
        for (int s = 0; s < 8; s++) {
            int idx = tid + s * 256;
            int n = idx >> 4, p = idx & 15;
            size_t o = (size_t)(col0 + n) * 64 + kb * 16 + p;
            Bs_h[n * 19 + p] = g_bh[o];
            Bs_l[n * 19 + p] = g_bl[o];
        }
        __syncthreads();

#pragma unroll
        for (int ki = 0; ki < 2; ki++) {
            int pb = ki * 8;
            uint32_t ah[2][4], al[2][4];
#pragma unroll
            for (int mi = 0; mi < 2; mi++) {
                int r0 = (wm * 32 + mi * 16 + g) * 18;
                int r1 = r0 + 8 * 18;
                ah[mi][0] = As_h[r0 + pb + t];     ah[mi][1] = As_h[r1 + pb + t];
                ah[mi][2] = As_h[r0 + pb + 4 + t]; ah[mi][3] = As_h[r1 + pb + 4 + t];
                al[mi][0] = As_l[r0 + pb + t];     al[mi][1] = As_l[r1 + pb + t];
                al[mi][2] = As_l[r0 + pb + 4 + t]; al[mi][3] = As_l[r1 + pb + 4 + t];
            }
#pragma unroll
            for (int ni = 0; ni < 8; ni++) {
                int n = (wn * 64 + ni * 8 + g) * 19;
                uint32_t bh0 = Bs_h[n + pb + t], bh1 = Bs_h[n + pb + 4 + t];
                uint32_t bl0 = Bs_l[n + pb + t], bl1 = Bs_l[n + pb + 4 + t];
#pragma unroll
                for (int mi = 0; mi < 2; mi++) {
                    mma16816(c[mi][ni], ah[mi], bh0, bh1);   // hi*hi
                    mma16816(c[mi][ni], ah[mi], bl0, bl1);   // hi*lo
                    mma16816(c[mi][ni], al[mi], bh0, bh1);   // lo*hi
                }
            }
        }
        __syncthreads();
    }

#pragma unroll
    for (int mi = 0; mi < 2; mi++) {
        int row = row0 + wm * 32 + mi * 16 + g;
#pragma unroll
        for (int ni = 0; ni < 8; ni++) {
            int col = col0 + wn * 64 + ni * 8 + 2 * t;
            float bx = __ldg(&bias[col]), by = __ldg(&bias[col + 1]);
            if (row < NN) {
                float2 v0 = make_float2(c[mi][ni][0] + bx, c[mi][ni][1] + by);
                *(float2*)&g_x[(size_t)row * KD + col] = v0;
                __half2 hb = __floats2half2_rn(v0.x, v0.y);
                g_xh[(size_t)row * (KD / 2) + (col >> 1)] = *(uint32_t*)&hb;
            }
            if (row + 8 < NN) {
                float2 v1 = make_float2(c[mi][ni][2] + bx, c[mi][ni][3] + by);
                *(float2*)&g_x[(size_t)(row + 8) * KD + col] = v1;
                __half2 hb = __floats2half2_rn(v1.x, v1.y);
                g_xh[(size_t)(row + 8) * (KD / 2) + (col >> 1)] = *(uint32_t*)&hb;
            }
        }
    }
}

// ---------------- kernel: degree histogram over dst ----------------
__global__ void k_hist(const int* __restrict__ ei) {
    int e = blockIdx.x * blockDim.x + threadIdx.x;
    if (e < EE) atomicAdd(&g_deg[ei[EE + e]], 1);
}

// ---------------- scan ----------------
__device__ __forceinline__ int block_scan_256(int v, int* wsum) {
    int lane = threadIdx.x & 31, wid = threadIdx.x >> 5;
    int x = v;
#pragma unroll
    for (int s = 1; s < 32; s <<= 1) {
        int y = __shfl_up_sync(0xffffffffu, x, s);
        if (lane >= s) x += y;
    }
    if (lane == 31) wsum[wid] = x;
    __syncthreads();
    if (wid == 0) {
        int y = (lane < 8) ? wsum[lane] : 0;
#pragma unroll
        for (int s = 1; s < 8; s <<= 1) {
            int z = __shfl_up_sync(0xffffffffu, y, s);
            if (lane >= s) y += z;
        }
        if (lane < 8) wsum[lane] = y;
    }
    __syncthreads();
    return x + (wid > 0 ? wsum[wid - 1] : 0);   // inclusive
}

__global__ void k_scanA() {   // per-block sums
    __shared__ int wsum[8];
    int i = blockIdx.x * 256 + threadIdx.x;
    int v = (i < NN) ? g_deg[i] : 0;
    int incl = block_scan_256(v, wsum);
    if (threadIdx.x == 255) g_bsum[blockIdx.x] = incl;
}

__global__ void k_scanC() {   // final offsets
    __shared__ int wsum[8];
    __shared__ int s_pre;
    int t = threadIdx.x, lane = t & 31, wid = t >> 5;

    int acc = 0;
    for (int i = t; i < blockIdx.x; i += 256) acc += g_bsum[i];
#pragma unroll
    for (int s = 16; s; s >>= 1) acc += __shfl_xor_sync(0xffffffffu, acc, s);
    if (lane == 0) wsum[wid] = acc;
    __syncthreads();
    if (t == 0) {
        int tot = 0;
#pragma unroll
        for (int w = 0; w < 8; w++) tot += wsum[w];
        s_pre = tot;
    }
    __syncthreads();
    int pre = s_pre;
    __syncthreads();

    int i = blockIdx.x * 256 + t;
    int v = (i < NN) ? g_deg[i] : 0;
    int incl = block_scan_256(v, wsum);
    if (i < NN) g_off[i + 1] = incl + pre;
    if (i == 0) g_off[0] = 0;
}

// ---------------- kernel: scatter edges into CSR ----------------
__global__ void k_scatter(const int* __restrict__ ei, const int* __restrict__ et) {
    int e = blockIdx.x * blockDim.x + threadIdx.x;
    if (e < EE) {
        int dst = ei[EE + e];
        int pos = g_off[dst] + atomicAdd(&g_cur[dst], 1);
        g_edg[pos] = ei[e] | (et[e] << 17);
    }
}

// ---------------- aggregation: per-edge step (all 3 factors) ----------------
__device__ __forceinline__ void agg_one(
    float4 xi0, float4 xi1, float4 xi2,
    float4 xj0, float4 xj1, float4 xj2,
    int et, int lane,
    const float* __restrict__ init_rel, const float* __restrict__ loop_rel,
    const float* __restrict__ rel_weight,
    float4& acc0, float4& acc1, float4& acc2,
    float& den0, float& den1, float& den2)
{
    const float4* w4 = (const float4*)(rel_weight + (size_t)et * (KK * DD));
    const float4* r4 = (const float4*)((et < LOOP_ET) ? (init_rel + (size_t)et * DD)
                                                      : loop_rel);
    float4 r  = __ldg(r4 + lane);
    float4 w0 = __ldg(w4 + lane);
    float4 w1 = __ldg(w4 + 32 + lane);
    float4 w2 = __ldg(w4 + 64 + lane);

    float4 jw0 = f4mul(xj0, w0);
    float4 jw1 = f4mul(xj1, w1);
    float4 jw2 = f4mul(xj2, w2);

    float p0 = dot4m(f4mul(xi0, w0), jw0);
    float p1 = dot4m(f4mul(xi1, w1), jw1);
    float p2 = dot4m(f4mul(xi2, w2), jw2);
#pragma unroll
    for (int s = 16; s; s >>= 1) {
        p0 += __shfl_xor_sync(0xffffffffu, p0, s);
        p1 += __shfl_xor_sync(0xffffffffu, p1, s);
        p2 += __shfl_xor_sync(0xffffffffu, p2, s);
    }
    float a0 = p0 > 0.f ? p0 : NEG * p0;
    float a1 = p1 > 0.f ? p1 : NEG * p1;
    float a2 = p2 > 0.f ? p2 : NEG * p2;
    float e0 = __expf(a0), e1 = __expf(a1), e2 = __expf(a2);
    den0 += e0; den1 += e1; den2 += e2;

    float4 rp = make_float4(r.x + 1.f, r.y + 1.f, r.z + 1.f, r.w + 1.f);
    f4fma(acc0, f4mul(jw0, rp), e0);
    f4fma(acc1, f4mul(jw1, rp), e1);
    f4fma(acc2, f4mul(jw2, rp), e2);
}

// slot load: one edge's fp16 x_j (3x LDG.64) + type; predicated
#define LOADSLOT(S, idx) do {                                                 \
    if ((idx) < end) {                                                        \
        int pp = g_edg[(idx)];                                                \
        S##et = pp >> 17;                                                     \
        const uint2* xs = (const uint2*)g_xh + (size_t)(pp & 0x1FFFF) * 96;   \
        S##u0 = __ldcg(xs + lane);                                            \
        S##u1 = __ldcg(xs + 32 + lane);                                       \
        S##u2 = __ldcg(xs + 64 + lane);                                       \
    }                                                                         \
} while (0)

#define PROCSLOT(S)                                                           \
    agg_one(xi0, xi1, xi2, h2x4(S##u0), h2x4(S##u1), h2x4(S##u2), S##et,      \
            lane, init_rel, loop_rel, rel_weight,                             \
            acc0, acc1, acc2, den0, den1, den2)

// ---------------- kernel: aggregation + fused BN stats ----------------
// 128 threads = 4 warps = 4 nodes per CTA; 12500 CTAs exactly cover NN.
__global__ __launch_bounds__(128) void k_agg(const float* __restrict__ init_rel,
                                             const float* __restrict__ loop_rel,
                                             const float* __restrict__ rel_weight) {
    __shared__ float s_sum[KD];
    __shared__ float s_sumsq[KD];
    for (int i = threadIdx.x; i < KD; i += 128) { s_sum[i] = 0.f; s_sumsq[i] = 0.f; }
    __syncthreads();

    int lane = threadIdx.x & 31;
    int node = blockIdx.x * 4 + (threadIdx.x >> 5);

    const float4* xrow = (const float4*)(g_x + (size_t)node * KD);
    float4 xi0 = __ldcg(xrow + lane);
    float4 xi1 = __ldcg(xrow + 32 + lane);
    float4 xi2 = __ldcg(xrow + 64 + lane);

    float4 acc0 = make_float4(0, 0, 0, 0);
    float4 acc1 = make_float4(0, 0, 0, 0);
    float4 acc2 = make_float4(0, 0, 0, 0);
    float den0 = 0.f, den1 = 0.f, den2 = 0.f;

    int beg = g_off[node], end = g_off[node + 1];

    uint2 au0, au1, au2; int aet;
    uint2 bu0, bu1, bu2; int bet;
    uint2 cu0, cu1, cu2; int cet;
    uint2 du0, du1, du2; int det;

    LOADSLOT(a, beg + 0);
    LOADSLOT(b, beg + 1);
    LOADSLOT(c, beg + 2);
    LOADSLOT(d, beg + 3);

    // self-loop (fp32 xi) while first gathers are in flight
    agg_one(xi0, xi1, xi2, xi0, xi1, xi2, LOOP_ET, lane,
            init_rel, loop_rel, rel_weight, acc0, acc1, acc2, den0, den1, den2);

    for (int e = beg; e < end; e += 4) {
        { PROCSLOT(a); LOADSLOT(a, e + 4); }
        if (e + 1 < end) { PROCSLOT(b); LOADSLOT(b, e + 5); }
        if (e + 2 < end) { PROCSLOT(c); LOADSLOT(c, e + 6); }
        if (e + 3 < end) { PROCSLOT(d); LOADSLOT(d, e + 7); }
    }

    float i0 = 1.f / (den0 + 1e-16f);
    float i1 = 1.f / (den1 + 1e-16f);
    float i2 = 1.f / (den2 + 1e-16f);
    float4 o0 = make_float4(acc0.x * i0, acc0.y * i0, acc0.z * i0, acc0.w * i0);
    float4 o1 = make_float4(acc1.x * i1, acc1.y * i1, acc1.z * i1, acc1.w * i1);
    float4 o2 = make_float4(acc2.x * i2, acc2.y * i2, acc2.z * i2, acc2.w * i2);

    float4* orow = (float4*)(g_out + (size_t)node * KD);
    orow[lane]      = o0;
    orow[32 + lane] = o1;
    orow[64 + lane] = o2;

    // fused BN stats: accumulate into shared, then one global atomic per col
    int c0 = 4 * lane;
#pragma unroll
    for (int j = 0; j < 4; j++) {
        float v0 = (&o0.x)[j], v1 = (&o1.x)[j], v2 = (&o2.x)[j];
        atomicAdd(&s_sum[c0 + j],           v0);
        atomicAdd(&s_sumsq[c0 + j],         v0 * v0);
        atomicAdd(&s_sum[128 + c0 + j],     v1);
        atomicAdd(&s_sumsq[128 + c0 + j],   v1 * v1);
        atomicAdd(&s_sum[256 + c0 + j],     v2);
        atomicAdd(&s_sumsq[256 + c0 + j],   v2 * v2);
    }
    __syncthreads();
    for (int i = threadIdx.x; i < KD; i += 128) {
        atomicAdd(&g_sum[i],   s_sum[i]);
        atomicAdd(&g_sumsq[i], s_sumsq[i]);
    }
}

// ---------------- kernel: finalize BN coefficients ----------------
__global__ void k_bnfinal(const float* __restrict__ gamma, const float* __restrict__ beta) {
    int c = threadIdx.x;
    if (c < KD) {
        float mu = g_sum[c] / (float)NN;
        float var = g_sumsq[c] / (float)NN - mu * mu;
        float a = gamma[c] * rsqrtf(var + BN_EPS);
        g_a[c] = a;
        g_b[c] = beta[c] - mu * a;
    }
}

// ---------------- kernel: normalize + tanh -> d_out ----------------
__global__ void k_apply(float* __restrict__ out) {
    int i = blockIdx.x * blockDim.x + threadIdx.x;   // float4 index
    if (i < NN * (KD / 4)) {
        int c4 = (i % (KD / 4)) * 4;
        float4 v = *(const float4*)&g_out[(size_t)i * 4];
        float4 y;
        y.x = fast_tanh(v.x * g_a[c4 + 0] + g_b[c4 + 0]);
        y.y = fast_tanh(v.y * g_a[c4 + 1] + g_b[c4 + 1]);
        y.z = fast_tanh(v.z * g_a[c4 + 2] + g_b[c4 + 2]);
        y.w = fast_tanh(v.w * g_a[c4 + 3] + g_b[c4 + 3]);
        ((float4*)out)[i] = y;
    }
}

// ---------------- launch ----------------
extern "C" void kernel_launch(void* const* d_in, const int* in_sizes, int n_in,
                              void* d_out, int out_size) {
    const float* init_embed = (const float*)d_in[0];
    const float* init_rel   = (const float*)d_in[1];
    const float* pca_w      = (const float*)d_in[2];
    const float* pca_b      = (const float*)d_in[3];
    const float* loop_rel   = (const float*)d_in[4];
    const float* rel_weight = (const float*)d_in[5];
    const float* bn_gamma   = (const float*)d_in[6];
    const float* bn_beta    = (const float*)d_in[7];
    const int*   edge_index = (const int*)d_in[8];
    const int*   edge_type  = (const int*)d_in[9];
    float* out = (float*)d_out;

    k_zero<<<(NN + 255) / 256, 256>>>();                          // idx 0
    k_hist<<<(EE + 255) / 256, 256>>>(edge_index);                // idx 1
    k_split<<<(NA_PAIRS + NB_PAIRS + 255) / 256, 256>>>(init_embed, pca_w); // idx 2

    dim3 gg((NN + 127) / 128, KD / 128);
    k_gemm<<<gg, 256>>>(pca_b);                                   // idx 3 <- ncu capture

    k_scanA<<<NBLK, 256>>>();                                     // idx 4
    k_scanC<<<NBLK, 256>>>();                                     // idx 5
    k_scatter<<<(EE + 255) / 256, 256>>>(edge_index, edge_type);  // idx 6

    k_agg<<<NN / 4, 128>>>(init_rel, loop_rel, rel_weight);       // idx 7

    k_bnfinal<<<1, 384>>>(bn_gamma, bn_beta);
    k_apply<<<(NN * (KD / 4) + 255) / 256, 256>>>(out);
}

// round 12
// speedup vs baseline: 1.1554x; 1.0649x over previous
#include <cuda_runtime.h>
#include <cuda_bf16.h>
#include <cuda_fp16.h>
#include <cstdint>

#define NN 50000
#define EE 500000
#define KK 3
#define DD 128
#define KD 384          // K*D
#define LOOP_ET 100     // 2R
#define NETS 101        // 2R+1
#define NEG 0.2f
#define BN_EPS 1e-5f
#define NBLK 196        // ceil(NN/256)

// ---------------- scratch (static __device__ globals; no runtime alloc) ----------------
__device__ uint32_t g_xh[(size_t)NN * (KD/2)];   // PCA output fp16x2 [N, K*D/2]
__device__ float    g_out[(size_t)NN * KD];      // aggregated pre-BN
__device__ uint32_t g_ah[(size_t)NN * 64];       // A hi bf16 pairs [N][64]
__device__ uint32_t g_al[(size_t)NN * 64];       // A lo
__device__ uint32_t g_bh[(size_t)KD * 64];       // B hi, transposed [n][kpair]
__device__ uint32_t g_bl[(size_t)KD * 64];       // B lo
__device__ float    g_rw1[NETS * KD];            // w*(1+r) fp32 [et][k][d]
__device__ uint32_t g_w2h[NETS * (KD/2)];        // (64w)^2 as h2 [et][k][d/2]
__device__ int   g_deg[NN];
__device__ int   g_off[NN + 1];
__device__ int   g_cur[NN];
__device__ int   g_edg[EE];                      // packed: src | (et<<17)
__device__ int   g_bsum[NBLK];
__device__ float g_sum[KD];
__device__ float g_sumsq[KD];
__device__ float g_a[KD];
__device__ float g_b[KD];

// ---------------- helpers ----------------
__device__ __forceinline__ float4 f4mul(float4 a, float4 b) {
    return make_float4(a.x * b.x, a.y * b.y, a.z * b.z, a.w * b.w);
}
__device__ __forceinline__ void f4fma(float4& acc, float4 m, float s) {
    acc.x += m.x * s; acc.y += m.y * s; acc.z += m.z * s; acc.w += m.w * s;
}
__device__ __forceinline__ float fast_tanh(float x) {
    float y;
    asm("tanh.approx.f32 %0, %1;" : "=f"(y) : "f"(x));
    return y;
}
__device__ __forceinline__ __half2 u2h(uint32_t u) {
    return *reinterpret_cast<__half2*>(&u);
}
__device__ __forceinline__ float4 h2x4(uint2 u) {
    float2 a = __half22float2(u2h(u.x));
    float2 b = __half22float2(u2h(u.y));
    return make_float4(a.x, a.y, b.x, b.y);
}
// scaled dot: sum over 4 dims of xi*xj*(64w)^2  (h2 math; result = 4096*partial)
__device__ __forceinline__ float dot_h2(uint2 xi, uint2 xj, uint2 w2) {
    __half2 a = __hmul2(u2h(xi.x), u2h(xj.x));
    __half2 b = __hmul2(u2h(xi.y), u2h(xj.y));
    __half2 t = __hmul2(a, u2h(w2.x));
    t = __hfma2(b, u2h(w2.y), t);
    float2 f = __half22float2(t);
    return f.x + f.y;
}

// ---------------- bf16 split helpers (GEMM inputs) ----------------
__device__ __forceinline__ void split2(float x, float y, uint32_t& h, uint32_t& l) {
    __nv_bfloat16 hx = __float2bfloat16_rn(x);
    __nv_bfloat16 hy = __float2bfloat16_rn(y);
    float rx = x - __bfloat162float(hx);
    float ry = y - __bfloat162float(hy);
    __nv_bfloat16 lx = __float2bfloat16_rn(rx);
    __nv_bfloat16 ly = __float2bfloat16_rn(ry);
    uint16_t uhx = *(uint16_t*)&hx, uhy = *(uint16_t*)&hy;
    uint16_t ulx = *(uint16_t*)&lx, uly = *(uint16_t*)&ly;
    h = (uint32_t)uhx | ((uint32_t)uhy << 16);
    l = (uint32_t)ulx | ((uint32_t)uly << 16);
}

__device__ __forceinline__ void mma16816(float* c, const uint32_t* a,
                                         uint32_t b0, uint32_t b1) {
    asm volatile(
        "mma.sync.aligned.m16n8k16.row.col.f32.bf16.bf16.f32 "
        "{%0,%1,%2,%3}, {%4,%5,%6,%7}, {%8,%9}, {%0,%1,%2,%3};"
        : "+f"(c[0]), "+f"(c[1]), "+f"(c[2]), "+f"(c[3])
        : "r"(a[0]), "r"(a[1]), "r"(a[2]), "r"(a[3]), "r"(b0), "r"(b1));
}

// ---------------- kernel: zero scratch counters ----------------
__global__ void k_zero() {
    int i = blockIdx.x * blockDim.x + threadIdx.x;
    if (i < NN) { g_deg[i] = 0; g_cur[i] = 0; }
    if (i < KD) { g_sum[i] = 0.f; g_sumsq[i] = 0.f; }
}

// ---------------- kernel: pre-split A/B + build rel tables ----------------
#define NA_PAIRS (NN * 64)
#define NB_PAIRS (KD * 64)
#define NW1 (NETS * KD)        // 38784 fp32
#define NW2 (NETS * (KD/2))    // 19392 uint32 (h2 pairs)
__global__ void k_split(const float* __restrict__ A, const float* __restrict__ B,
                        const float* __restrict__ init_rel,
                        const float* __restrict__ loop_rel,
                        const float* __restrict__ rel_weight) {
    int i = blockIdx.x * blockDim.x + threadIdx.x;
    if (i < NA_PAIRS) {
        float2 v = *(const float2*)&A[(size_t)i * 2];
        uint32_t h, l;
        split2(v.x, v.y, h, l);
        g_ah[i] = h; g_al[i] = l;
    } else if (i < NA_PAIRS + NB_PAIRS) {
        int j = i - NA_PAIRS;          // j = n*64 + p
        int n = j >> 6, p = j & 63;
        float b0 = B[(size_t)(2 * p) * KD + n];
        float b1 = B[(size_t)(2 * p + 1) * KD + n];
        uint32_t h, l;
        split2(b0, b1, h, l);
        g_bh[j] = h; g_bl[j] = l;
    } else if (i < NA_PAIRS + NB_PAIRS + NW1) {
        int j = i - (NA_PAIRS + NB_PAIRS);   // [0, 101*384)
        int et = j / KD;
        int d = j & 127;                     // dim within factor
        float w = rel_weight[j];
        float r = (et < LOOP_ET) ? init_rel[et * DD + d] : loop_rel[d];
        g_rw1[j] = w * (1.f + r);
    } else if (i < NA_PAIRS + NB_PAIRS + NW1 + NW2) {
        int j = i - (NA_PAIRS + NB_PAIRS + NW1); // [0, 101*192)
        int et = j / (KD / 2);
        int rem = j - et * (KD / 2);             // k*64 + d2
        int base = et * KD + 2 * rem;            // element index of pair start
        float w0 = rel_weight[base] * 64.f;
        float w1 = rel_weight[base + 1] * 64.f;
        __half2 h = __floats2half2_rn(w0 * w0, w1 * w1);
        g_w2h[j] = *(uint32_t*)&h;
    }
}

// ---------------- kernel: x = init_embed @ pca_w + pca_b  (bf16 3xMMA) ----------------
// writes ONLY the fp16 table g_xh.
__global__ __launch_bounds__(256, 2) void k_gemm(const float* __restrict__ bias) {
    __shared__ uint32_t As_h[128 * 18], As_l[128 * 18];
    __shared__ uint32_t Bs_h[128 * 19], Bs_l[128 * 19];
    int tid = threadIdx.x;
    int warp = tid >> 5, lane = tid & 31;
    int g = lane >> 2, t = lane & 3;
    int wm = warp >> 1, wn = warp & 1;
    int row0 = blockIdx.x * 128;
    int col0 = blockIdx.y * 128;

    float c[2][8][4];
#pragma unroll
    for (int mi = 0; mi < 2; mi++)
#pragma unroll
        for (int ni = 0; ni < 8; ni++)
#pragma unroll
            for (int j = 0; j < 4; j++) c[mi][ni][j] = 0.f;

    for (int kb = 0; kb < 4; kb++) {
#pragma unroll
        for (int s = 0; s < 8; s++) {
            int idx = tid + s * 256;
            int r = idx >> 4, p = idx & 15;
            int gr = row0 + r;
            uint32_t h = 0, l = 0;
            if (gr < NN) {
                size_t o = (size_t)gr * 64 + kb * 16 + p;
                h = g_ah[o]; l = g_al[o];
            }
            As_h[r * 18 + p] = h;
            As_l[r * 18 + p] = l;
        }
#pragma unroll
        for (int s = 0; s < 8; s++) {
            int idx = tid + s * 256;
            int n = idx >> 4, p = idx & 15;
            size_t o = (size_t)(col0 + n) * 64 + kb * 16 + p;
            Bs_h[n * 19 + p] = g_bh[o];
            Bs_l[n * 19 + p] = g_bl[o];
        }
        __syncthreads();

#pragma unroll
        for (int ki = 0; ki < 2; ki++) {
            int pb = ki * 8;
            uint32_t ah[2][4], al[2][4];
#pragma unroll
            for (int mi = 0; mi < 2; mi++) {
                int r0 = (wm * 32 + mi * 16 + g) * 18;
                int r1 = r0 + 8 * 18;
                ah[mi][0] = As_h[r0 + pb + t];     ah[mi][1] = As_h[r1 + pb + t];
                ah[mi][2] = As_h[r0 + pb + 4 + t]; ah[mi][3] = As_h[r1 + pb + 4 + t];
                al[mi][0] = As_l[r0 + pb + t];     al[mi][1] = As_l[r1 + pb + t];
                al[mi][2] = As_l[r0 + pb + 4 + t]; al[mi][3] = As_l[r1 + pb + 4 + t];
            }
#pragma unroll
            for (int ni = 0; ni < 8; ni++) {
                int n = (wn * 64 + ni * 8 + g) * 19;
                uint32_t bh0 = Bs_h[n + pb + t], bh1 = Bs_h[n + pb + 4 + t];
                uint32_t bl0 = Bs_l[n + pb + t], bl1 = Bs_l[n + pb + 4 + t];
#pragma unroll
                for (int mi = 0; mi < 2; mi++) {
                    mma16816(c[mi][ni], ah[mi], bh0, bh1);   // hi*hi
                    mma16816(c[mi][ni], ah[mi], bl0, bl1);   // hi*lo
                    mma16816(c[mi][ni], al[mi], bh0, bh1);   // lo*hi
                }
            }
        }
        __syncthreads();
    }

#pragma unroll
    for (int mi = 0; mi < 2; mi++) {
        int row = row0 + wm * 32 + mi * 16 + g;
#pragma unroll
        for (int ni = 0; ni < 8; ni++) {
            int col = col0 + wn * 64 + ni * 8 + 2 * t;
            float bx = __ldg(&bias[col]), by = __ldg(&bias[col + 1]);
            if (row < NN) {
                __half2 hb = __floats2half2_rn(c[mi][ni][0] + bx, c[mi][ni][1] + by);
                g_xh[(size_t)row * (KD / 2) + (col >> 1)] = *(uint32_t*)&hb;
            }
            if (row + 8 < NN) {
                __half2 hb = __floats2half2_rn(c[mi][ni][2] + bx, c[mi][ni][3] + by);
                g_xh[(size_t)(row + 8) * (KD / 2) + (col >> 1)] = *(uint32_t*)&hb;
            }
        }
    }
}

// ---------------- kernel: degree histogram over dst ----------------
__global__ void k_hist(const int* __restrict__ ei) {
    int e = blockIdx.x * blockDim.x + threadIdx.x;
    if (e < EE) atomicAdd(&g_deg[ei[EE + e]], 1);
}

// ---------------- scan ----------------
__device__ __forceinline__ int block_scan_256(int v, int* wsum) {
    int lane = threadIdx.x & 31, wid = threadIdx.x >> 5;
    int x = v;
#pragma unroll
    for (int s = 1; s < 32; s <<= 1) {
        int y = __shfl_up_sync(0xffffffffu, x, s);
        if (lane >= s) x += y;
    }
    if (lane == 31) wsum[wid] = x;
    __syncthreads();
    if (wid == 0) {
        int y = (lane < 8) ? wsum[lane] : 0;
#pragma unroll
        for (int s = 1; s < 8; s <<= 1) {
            int z = __shfl_up_sync(0xffffffffu, y, s);
            if (lane >= s) y += z;
        }
        if (lane < 8) wsum[lane] = y;
    }
    __syncthreads();
    return x + (wid > 0 ? wsum[wid - 1] : 0);   // inclusive
}

__global__ void k_scanA() {   // per-block sums
    __shared__ int wsum[8];
    int i = blockIdx.x * 256 + threadIdx.x;
    int v = (i < NN) ? g_deg[i] : 0;
    int incl = block_scan_256(v, wsum);
    if (threadIdx.x == 255) g_bsum[blockIdx.x] = incl;
}

__global__ void k_scanC() {   // final offsets
    __shared__ int wsum[8];
    __shared__ int s_pre;
    int t = threadIdx.x, lane = t & 31, wid = t >> 5;

    int acc = 0;
    for (int i = t; i < blockIdx.x; i += 256) acc += g_bsum[i];
#pragma unroll
    for (int s = 16; s; s >>= 1) acc += __shfl_xor_sync(0xffffffffu, acc, s);
    if (lane == 0) wsum[wid] = acc;
    __syncthreads();
    if (t == 0) {
        int tot = 0;
#pragma unroll
        for (int w = 0; w < 8; w++) tot += wsum[w];
        s_pre = tot;
    }
    __syncthreads();
    int pre = s_pre;
    __syncthreads();

    int i = blockIdx.x * 256 + t;
    int v = (i < NN) ? g_deg[i] : 0;
    int incl = block_scan_256(v, wsum);
    if (i < NN) g_off[i + 1] = incl + pre;
    if (i == 0) g_off[0] = 0;
}

// ---------------- kernel: scatter edges into CSR ----------------
__global__ void k_scatter(const int* __restrict__ ei, const int* __restrict__ et) {
    int e = blockIdx.x * blockDim.x + threadIdx.x;
    if (e < EE) {
        int dst = ei[EE + e];
        int pos = g_off[dst] + atomicAdd(&g_cur[dst], 1);
        g_edg[pos] = ei[e] | (et[e] << 17);
    }
}

// ---------------- aggregation: per-edge step ----------------
// attention dot via h2 tables (scaled 4096); message via rw1 = w*(1+r)
__device__ __forceinline__ void agg_one(
    uint2 xih0, uint2 xih1, uint2 xih2,
    uint2 xjh0, uint2 xjh1, uint2 xjh2,
    int et, int lane,
    float4& acc0, float4& acc1, float4& acc2,
    float& den0, float& den1, float& den2)
{
    const uint2* w2p = (const uint2*)g_w2h + (size_t)et * 96 + lane;
    uint2 w20 = __ldg(w2p);
    uint2 w21 = __ldg(w2p + 32);
    uint2 w22 = __ldg(w2p + 64);

    float p0 = dot_h2(xih0, xjh0, w20);
    float p1 = dot_h2(xih1, xjh1, w21);
    float p2 = dot_h2(xih2, xjh2, w22);
#pragma unroll
    for (int s = 16; s; s >>= 1) {
        p0 += __shfl_xor_sync(0xffffffffu, p0, s);
        p1 += __shfl_xor_sync(0xffffffffu, p1, s);
        p2 += __shfl_xor_sync(0xffffffffu, p2, s);
    }
    const float inv = 1.f / 4096.f;
    float a0 = p0 * inv, a1 = p1 * inv, a2 = p2 * inv;
    a0 = a0 > 0.f ? a0 : NEG * a0;
    a1 = a1 > 0.f ? a1 : NEG * a1;
    a2 = a2 > 0.f ? a2 : NEG * a2;
    float e0 = __expf(a0), e1 = __expf(a1), e2 = __expf(a2);
    den0 += e0; den1 += e1; den2 += e2;

    const float4* rw = (const float4*)g_rw1 + (size_t)et * 96 + lane;
    f4fma(acc0, f4mul(h2x4(xjh0), __ldg(rw)),      e0);
    f4fma(acc1, f4mul(h2x4(xjh1), __ldg(rw + 32)), e1);
    f4fma(acc2, f4mul(h2x4(xjh2), __ldg(rw + 64)), e2);
}

// slot load: one edge's fp16 x_j (3x LDG.64) + type; predicated
#define LOADSLOT(S, idx) do {                                                 \
    if ((idx) < end) {                                                        \
        int pp = g_edg[(idx)];                                                \
        S##et = pp >> 17;                                                     \
        const uint2* xs = (const uint2*)g_xh + (size_t)(pp & 0x1FFFF) * 96;   \
        S##u0 = __ldcg(xs + lane);                                            \
        S##u1 = __ldcg(xs + 32 + lane);                                       \
        S##u2 = __ldcg(xs + 64 + lane);                                       \
    }                                                                         \
} while (0)

#define PROCSLOT(S)                                                           \
    agg_one(xih0, xih1, xih2, S##u0, S##u1, S##u2, S##et, lane,               \
            acc0, acc1, acc2, den0, den1, den2)

// ---------------- kernel: aggregation + fused BN stats ----------------
// 128 threads = 4 warps = 4 nodes per CTA; 12500 CTAs exactly cover NN.
__global__ __launch_bounds__(128) void k_agg() {
    __shared__ float s_sum[KD];
    __shared__ float s_sumsq[KD];
    for (int i = threadIdx.x; i < KD; i += 128) { s_sum[i] = 0.f; s_sumsq[i] = 0.f; }
    __syncthreads();

    int lane = threadIdx.x & 31;
    int node = blockIdx.x * 4 + (threadIdx.x >> 5);

    const uint2* xrow = (const uint2*)g_xh + (size_t)node * 96;
    uint2 xih0 = __ldcg(xrow + lane);
    uint2 xih1 = __ldcg(xrow + 32 + lane);
    uint2 xih2 = __ldcg(xrow + 64 + lane);

    float4 acc0 = make_float4(0, 0, 0, 0);
    float4 acc1 = make_float4(0, 0, 0, 0);
    float4 acc2 = make_float4(0, 0, 0, 0);
    float den0 = 0.f, den1 = 0.f, den2 = 0.f;

    int beg = g_off[node], end = g_off[node + 1];

    uint2 au0, au1, au2; int aet;
    uint2 bu0, bu1, bu2; int bet;
    uint2 cu0, cu1, cu2; int cet;
    uint2 du0, du1, du2; int det;

    LOADSLOT(a, beg + 0);
    LOADSLOT(b, beg + 1);
    LOADSLOT(c, beg + 2);
    LOADSLOT(d, beg + 3);

    // self-loop (xj = xi) while first gathers are in flight
    agg_one(xih0, xih1, xih2, xih0, xih1, xih2, LOOP_ET, lane,
            acc0, acc1, acc2, den0, den1, den2);

    for (int e = beg; e < end; e += 4) {
        { PROCSLOT(a); LOADSLOT(a, e + 4); }
        if (e + 1 < end) { PROCSLOT(b); LOADSLOT(b, e + 5); }
        if (e + 2 < end) { PROCSLOT(c); LOADSLOT(c, e + 6); }
        if (e + 3 < end) { PROCSLOT(d); LOADSLOT(d, e + 7); }
    }

    float i0 = 1.f / (den0 + 1e-16f);
    float i1 = 1.f / (den1 + 1e-16f);
    float i2 = 1.f / (den2 + 1e-16f);
    float4 o0 = make_float4(acc0.x * i0, acc0.y * i0, acc0.z * i0, acc0.w * i0);
    float4 o1 = make_float4(acc1.x * i1, acc1.y * i1, acc1.z * i1, acc1.w * i1);
    float4 o2 = make_float4(acc2.x * i2, acc2.y * i2, acc2.z * i2, acc2.w * i2);

    float4* orow = (float4*)(g_out + (size_t)node * KD);
    orow[lane]      = o0;
    orow[32 + lane] = o1;
    orow[64 + lane] = o2;

    // fused BN stats: accumulate into shared, then one global atomic per col
    int c0 = 4 * lane;
#pragma unroll
    for (int j = 0; j < 4; j++) {
        float v0 = (&o0.x)[j], v1 = (&o1.x)[j], v2 = (&o2.x)[j];
        atomicAdd(&s_sum[c0 + j],           v0);
        atomicAdd(&s_sumsq[c0 + j],         v0 * v0);
        atomicAdd(&s_sum[128 + c0 + j],     v1);
        atomicAdd(&s_sumsq[128 + c0 + j],   v1 * v1);
        atomicAdd(&s_sum[256 + c0 + j],     v2);
        atomicAdd(&s_sumsq[256 + c0 + j],   v2 * v2);
    }
    __syncthreads();
    for (int i = threadIdx.x; i < KD; i += 128) {
        atomicAdd(&g_sum[i],   s_sum[i]);
        atomicAdd(&g_sumsq[i], s_sumsq[i]);
    }
}

// ---------------- kernel: finalize BN coefficients ----------------
__global__ void k_bnfinal(const float* __restrict__ gamma, const float* __restrict__ beta) {
    int c = threadIdx.x;
    if (c < KD) {
        float mu = g_sum[c] / (float)NN;
        float var = g_sumsq[c] / (float)NN - mu * mu;
        float a = gamma[c] * rsqrtf(var + BN_EPS);
        g_a[c] = a;
        g_b[c] = beta[c] - mu * a;
    }
}

// ---------------- kernel: normalize + tanh -> d_out ----------------
__global__ void k_apply(float* __restrict__ out) {
    int i = blockIdx.x * blockDim.x + threadIdx.x;   // float4 index
    if (i < NN * (KD / 4)) {
        int c4 = (i % (KD / 4)) * 4;
        float4 v = *(const float4*)&g_out[(size_t)i * 4];
        float4 y;
        y.x = fast_tanh(v.x * g_a[c4 + 0] + g_b[c4 + 0]);
        y.y = fast_tanh(v.y * g_a[c4 + 1] + g_b[c4 + 1]);
        y.z = fast_tanh(v.z * g_a[c4 + 2] + g_b[c4 + 2]);
        y.w = fast_tanh(v.w * g_a[c4 + 3] + g_b[c4 + 3]);
        ((float4*)out)[i] = y;
    }
}

// ---------------- launch ----------------
extern "C" void kernel_launch(void* const* d_in, const int* in_sizes, int n_in,
                              void* d_out, int out_size) {
    const float* init_embed = (const float*)d_in[0];
    const float* init_rel   = (const float*)d_in[1];
    const float* pca_w      = (const float*)d_in[2];
    const float* pca_b      = (const float*)d_in[3];
    const float* loop_rel   = (const float*)d_in[4];
    const float* rel_weight = (const float*)d_in[5];
    const float* bn_gamma   = (const float*)d_in[6];
    const float* bn_beta    = (const float*)d_in[7];
    const int*   edge_index = (const int*)d_in[8];
    const int*   edge_type  = (const int*)d_in[9];
    float* out = (float*)d_out;

    k_zero<<<(NN + 255) / 256, 256>>>();                          // idx 0
    k_hist<<<(EE + 255) / 256, 256>>>(edge_index);                // idx 1
    k_split<<<(NA_PAIRS + NB_PAIRS + NW1 + NW2 + 255) / 256, 256>>>(
        init_embed, pca_w, init_rel, loop_rel, rel_weight);       // idx 2

    dim3 gg((NN + 127) / 128, KD / 128);
    k_gemm<<<gg, 256>>>(pca_b);                                   // idx 3 <- ncu capture

    k_scanA<<<NBLK, 256>>>();                                     // idx 4
    k_scanC<<<NBLK, 256>>>();                                     // idx 5
    k_scatter<<<(EE + 255) / 256, 256>>>(edge_index, edge_type);  // idx 6

    k_agg<<<NN / 4, 128>>>();                                     // idx 7

    k_bnfinal<<<1, 384>>>(bn_gamma, bn_beta);
    k_apply<<<(NN * (KD / 4) + 255) / 256, 256>>>(out);
}

// round 13
// speedup vs baseline: 1.1556x; 1.0001x over previous
#include <cuda_runtime.h>
#include <cuda_bf16.h>
#include <cuda_fp16.h>
#include <cstdint>

#define NN 50000
#define EE 500000
#define KK 3
#define DD 128
#define KD 384          // K*D
#define LOOP_ET 100     // 2R
#define NETS 101        // 2R+1
#define NEG 0.2f
#define BN_EPS 1e-5f
#define NBLK 196        // ceil(NN/256)

// ---------------- scratch (static __device__ globals; no runtime alloc) ----------------
__device__ uint32_t g_xh[(size_t)NN * (KD/2)];   // PCA output fp16x2 [N, K*D/2]
__device__ float    g_out[(size_t)NN * KD];      // aggregated pre-BN
__device__ uint32_t g_ah[(size_t)NN * 64];       // A hi bf16 pairs [N][64]
__device__ uint32_t g_al[(size_t)NN * 64];       // A lo
__device__ uint32_t g_bh[(size_t)KD * 64];       // B hi, transposed [n][kpair]
__device__ uint32_t g_bl[(size_t)KD * 64];       // B lo
__device__ float    g_rw1[NETS * KD];            // w*(1+r) fp32 [et][k][d]
__device__ uint32_t g_w2h[NETS * (KD/2)];        // (64w)^2 as h2 [et][k][d/2]
__device__ int   g_deg[NN];
__device__ int   g_off[NN + 1];
__device__ int   g_cur[NN];
__device__ int   g_edg[EE];                      // packed: src | (et<<17)
__device__ int   g_bsum[NBLK];
__device__ float g_sum[KD];
__device__ float g_sumsq[KD];
__device__ float g_a[KD];
__device__ float g_b[KD];

// ---------------- helpers ----------------
__device__ __forceinline__ float4 f4mul(float4 a, float4 b) {
    return make_float4(a.x * b.x, a.y * b.y, a.z * b.z, a.w * b.w);
}
__device__ __forceinline__ void f4fma(float4& acc, float4 m, float s) {
    acc.x += m.x * s; acc.y += m.y * s; acc.z += m.z * s; acc.w += m.w * s;
}
__device__ __forceinline__ float fast_tanh(float x) {
    float y;
    asm("tanh.approx.f32 %0, %1;" : "=f"(y) : "f"(x));
    return y;
}
__device__ __forceinline__ __half2 u2h(uint32_t u) {
    return *reinterpret_cast<__half2*>(&u);
}
__device__ __forceinline__ float4 h2x4(uint2 u) {
    float2 a = __half22float2(u2h(u.x));
    float2 b = __half22float2(u2h(u.y));
    return make_float4(a.x, a.y, b.x, b.y);
}
// scaled dot: sum over 4 dims of xi*xj*(64w)^2  (h2 math; result = 4096*partial)
__device__ __forceinline__ float dot_h2(uint2 xi, uint2 xj, uint2 w2) {
    __half2 a = __hmul2(u2h(xi.x), u2h(xj.x));
    __half2 b = __hmul2(u2h(xi.y), u2h(xj.y));
    __half2 t = __hmul2(a, u2h(w2.x));
    t = __hfma2(b, u2h(w2.y), t);
    float2 f = __half22float2(t);
    return f.x + f.y;
}

// ---------------- bf16 split helpers (GEMM inputs) ----------------
__device__ __forceinline__ void split2(float x, float y, uint32_t& h, uint32_t& l) {
    __nv_bfloat16 hx = __float2bfloat16_rn(x);
    __nv_bfloat16 hy = __float2bfloat16_rn(y);
    float rx = x - __bfloat162float(hx);
    float ry = y - __bfloat162float(hy);
    __nv_bfloat16 lx = __float2bfloat16_rn(rx);
    __nv_bfloat16 ly = __float2bfloat16_rn(ry);
    uint16_t uhx = *(uint16_t*)&hx, uhy = *(uint16_t*)&hy;
    uint16_t ulx = *(uint16_t*)&lx, uly = *(uint16_t*)&ly;
    h = (uint32_t)uhx | ((uint32_t)uhy << 16);
    l = (uint32_t)ulx | ((uint32_t)uly << 16);
}

__device__ __forceinline__ void mma16816(float* c, const uint32_t* a,
                                         uint32_t b0, uint32_t b1) {
    asm volatile(
        "mma.sync.aligned.m16n8k16.row.col.f32.bf16.bf16.f32 "
        "{%0,%1,%2,%3}, {%4,%5,%6,%7}, {%8,%9}, {%0,%1,%2,%3};"
        : "+f"(c[0]), "+f"(c[1]), "+f"(c[2]), "+f"(c[3])
        : "r"(a[0]), "r"(a[1]), "r"(a[2]), "r"(a[3]), "r"(b0), "r"(b1));
}

// ---------------- kernel: zero scratch counters ----------------
__global__ void k_zero() {
    int i = blockIdx.x * blockDim.x + threadIdx.x;
    if (i < NN) { g_deg[i] = 0; g_cur[i] = 0; }
    if (i < KD) { g_sum[i] = 0.f; g_sumsq[i] = 0.f; }
}

// ---------------- kernel: pre-split A/B + build rel tables ----------------
#define NA_PAIRS (NN * 64)
#define NB_PAIRS (KD * 64)
#define NW1 (NETS * KD)        // 38784 fp32
#define NW2 (NETS * (KD/2))    // 19392 uint32 (h2 pairs)
__global__ void k_split(const float* __restrict__ A, const float* __restrict__ B,
                        const float* __restrict__ init_rel,
                        const float* __restrict__ loop_rel,
                        const float* __restrict__ rel_weight) {
    int i = blockIdx.x * blockDim.x + threadIdx.x;
    if (i < NA_PAIRS) {
        float2 v = *(const float2*)&A[(size_t)i * 2];
        uint32_t h, l;
        split2(v.x, v.y, h, l);
        g_ah[i] = h; g_al[i] = l;
    } else if (i < NA_PAIRS + NB_PAIRS) {
        int j = i - NA_PAIRS;          // j = n*64 + p
        int n = j >> 6, p = j & 63;
        float b0 = B[(size_t)(2 * p) * KD + n];
        float b1 = B[(size_t)(2 * p + 1) * KD + n];
        uint32_t h, l;
        split2(b0, b1, h, l);
        g_bh[j] = h; g_bl[j] = l;
    } else if (i < NA_PAIRS + NB_PAIRS + NW1) {
        int j = i - (NA_PAIRS + NB_PAIRS);   // [0, 101*384)
        int et = j / KD;
        int d = j & 127;                     // dim within factor
        float w = rel_weight[j];
        float r = (et < LOOP_ET) ? init_rel[et * DD + d] : loop_rel[d];
        g_rw1[j] = w * (1.f + r);
    } else if (i < NA_PAIRS + NB_PAIRS + NW1 + NW2) {
        int j = i - (NA_PAIRS + NB_PAIRS + NW1); // [0, 101*192)
        int et = j / (KD / 2);
        int rem = j - et * (KD / 2);             // k*64 + d2
        int base = et * KD + 2 * rem;            // element index of pair start
        float w0 = rel_weight[base] * 64.f;
        float w1 = rel_weight[base + 1] * 64.f;
        __half2 h = __floats2half2_rn(w0 * w0, w1 * w1);
        g_w2h[j] = *(uint32_t*)&h;
    }
}

// ---------------- kernel: x = init_embed @ pca_w + pca_b  (bf16 3xMMA) ----------------
// writes ONLY the fp16 table g_xh.
__global__ __launch_bounds__(256, 2) void k_gemm(const float* __restrict__ bias) {
    __shared__ uint32_t As_h[128 * 18], As_l[128 * 18];
    __shared__ uint32_t Bs_h[128 * 19], Bs_l[128 * 19];
    int tid = threadIdx.x;
    int warp = tid >> 5, lane = tid & 31;
    int g = lane >> 2, t = lane & 3;
    int wm = warp >> 1, wn = warp & 1;
    int row0 = blockIdx.x * 128;
    int col0 = blockIdx.y * 128;

    float c[2][8][4];
#pragma unroll
    for (int mi = 0; mi < 2; mi++)
#pragma unroll
        for (int ni = 0; ni < 8; ni++)
#pragma unroll
            for (int j = 0; j < 4; j++) c[mi][ni][j] = 0.f;

    for (int kb = 0; kb < 4; kb++) {
#pragma unroll
        for (int s = 0; s < 8; s++) {
            int idx = tid + s * 256;
            int r = idx >> 4, p = idx & 15;
            int gr = row0 + r;
            uint32_t h = 0, l = 0;
            if (gr < NN) {
                size_t o = (size_t)gr * 64 + kb * 16 + p;
                h = g_ah[o]; l = g_al[o];
            }
            As_h[r * 18 + p] = h;
            As_l[r * 18 + p] = l;
        }
#pragma unroll
        for (int s = 0; s < 8; s++) {
            int idx = tid + s * 256;
            int n = idx >> 4, p = idx & 15;
            size_t o = (size_t)(col0 + n) * 64 + kb * 16 + p;
            Bs_h[n * 19 + p] = g_bh[o];
            Bs_l[n * 19 + p] = g_bl[o];
        }
        __syncthreads();

#pragma unroll
        for (int ki = 0; ki < 2; ki++) {
            int pb = ki * 8;
            uint32_t ah[2][4], al[2][4];
#pragma unroll
            for (int mi = 0; mi < 2; mi++) {
                int r0 = (wm * 32 + mi * 16 + g) * 18;
                int r1 = r0 + 8 * 18;
                ah[mi][0] = As_h[r0 + pb + t];     ah[mi][1] = As_h[r1 + pb + t];
                ah[mi][2] = As_h[r0 + pb + 4 + t]; ah[mi][3] = As_h[r1 + pb + 4 + t];
                al[mi][0] = As_l[r0 + pb + t];     al[mi][1] = As_l[r1 + pb + t];
                al[mi][2] = As_l[r0 + pb + 4 + t]; al[mi][3] = As_l[r1 + pb + 4 + t];
            }
#pragma unroll
            for (int ni = 0; ni < 8; ni++) {
                int n = (wn * 64 + ni * 8 + g) * 19;
                uint32_t bh0 = Bs_h[n + pb + t], bh1 = Bs_h[n + pb + 4 + t];
                uint32_t bl0 = Bs_l[n + pb + t], bl1 = Bs_l[n + pb + 4 + t];
#pragma unroll
                for (int mi = 0; mi < 2; mi++) {
                    mma16816(c[mi][ni], ah[mi], bh0, bh1);   // hi*hi
                    mma16816(c[mi][ni], ah[mi], bl0, bl1);   // hi*lo
                    mma16816(c[mi][ni], al[mi], bh0, bh1);   // lo*hi
                }
            }
        }
        __syncthreads();
    }

#pragma unroll
    for (int mi = 0; mi < 2; mi++) {
        int row = row0 + wm * 32 + mi * 16 + g;
#pragma unroll
        for (int ni = 0; ni < 8; ni++) {
            int col = col0 + wn * 64 + ni * 8 + 2 * t;
            float bx = __ldg(&bias[col]), by = __ldg(&bias[col + 1]);
            if (row < NN) {
                __half2 hb = __floats2half2_rn(c[mi][ni][0] + bx, c[mi][ni][1] + by);
                g_xh[(size_t)row * (KD / 2) + (col >> 1)] = *(uint32_t*)&hb;
            }
            if (row + 8 < NN) {
                __half2 hb = __floats2half2_rn(c[mi][ni][2] + bx, c[mi][ni][3] + by);
                g_xh[(size_t)(row + 8) * (KD / 2) + (col >> 1)] = *(uint32_t*)&hb;
            }
        }
    }
}

// ---------------- kernel: degree histogram over dst ----------------
__global__ void k_hist(const int* __restrict__ ei) {
    int e = blockIdx.x * blockDim.x + threadIdx.x;
    if (e < EE) atomicAdd(&g_deg[ei[EE + e]], 1);
}

// ---------------- scan ----------------
__device__ __forceinline__ int block_scan_256(int v, int* wsum) {
    int lane = threadIdx.x & 31, wid = threadIdx.x >> 5;
    int x = v;
#pragma unroll
    for (int s = 1; s < 32; s <<= 1) {
        int y = __shfl_up_sync(0xffffffffu, x, s);
        if (lane >= s) x += y;
    }
    if (lane == 31) wsum[wid] = x;
    __syncthreads();
    if (wid == 0) {
        int y = (lane < 8) ? wsum[lane] : 0;
#pragma unroll
        for (int s = 1; s < 8; s <<= 1) {
            int z = __shfl_up_sync(0xffffffffu, y, s);
            if (lane >= s) y += z;
        }
        if (lane < 8) wsum[lane] = y;
    }
    __syncthreads();
    return x + (wid > 0 ? wsum[wid - 1] : 0);   // inclusive
}

__global__ void k_scanA() {   // per-block sums
    __shared__ int wsum[8];
    int i = blockIdx.x * 256 + threadIdx.x;
    int v = (i < NN) ? g_deg[i] : 0;
    int incl = block_scan_256(v, wsum);
    if (threadIdx.x == 255) g_bsum[blockIdx.x] = incl;
}

__global__ void k_scanC() {   // final offsets
    __shared__ int wsum[8];
    __shared__ int s_pre;
    int t = threadIdx.x, lane = t & 31, wid = t >> 5;

    int acc = 0;
    for (int i = t; i < blockIdx.x; i += 256) acc += g_bsum[i];
#pragma unroll
    for (int s = 16; s; s >>= 1) acc += __shfl_xor_sync(0xffffffffu, acc, s);
    if (lane == 0) wsum[wid] = acc;
    __syncthreads();
    if (t == 0) {
        int tot = 0;
#pragma unroll
        for (int w = 0; w < 8; w++) tot += wsum[w];
        s_pre = tot;
    }
    __syncthreads();
    int pre = s_pre;
    __syncthreads();

    int i = blockIdx.x * 256 + t;
    int v = (i < NN) ? g_deg[i] : 0;
    int incl = block_scan_256(v, wsum);
    if (i < NN) g_off[i + 1] = incl + pre;
    if (i == 0) g_off[0] = 0;
}

// ---------------- kernel: scatter edges into CSR ----------------
__global__ void k_scatter(const int* __restrict__ ei, const int* __restrict__ et) {
    int e = blockIdx.x * blockDim.x + threadIdx.x;
    if (e < EE) {
        int dst = ei[EE + e];
        int pos = g_off[dst] + atomicAdd(&g_cur[dst], 1);
        g_edg[pos] = ei[e] | (et[e] << 17);
    }
}

// ---------------- aggregation: per-edge step ----------------
// attention dot via h2 tables (scaled 4096); message via rw1 = w*(1+r)
__device__ __forceinline__ void agg_one(
    uint2 xih0, uint2 xih1, uint2 xih2,
    uint2 xjh0, uint2 xjh1, uint2 xjh2,
    int et, int lane,
    float4& acc0, float4& acc1, float4& acc2,
    float& den0, float& den1, float& den2)
{
    const uint2* w2p = (const uint2*)g_w2h + (size_t)et * 96 + lane;
    uint2 w20 = __ldg(w2p);
    uint2 w21 = __ldg(w2p + 32);
    uint2 w22 = __ldg(w2p + 64);

    float p0 = dot_h2(xih0, xjh0, w20);
    float p1 = dot_h2(xih1, xjh1, w21);
    float p2 = dot_h2(xih2, xjh2, w22);
#pragma unroll
    for (int s = 16; s; s >>= 1) {
        p0 += __shfl_xor_sync(0xffffffffu, p0, s);
        p1 += __shfl_xor_sync(0xffffffffu, p1, s);
        p2 += __shfl_xor_sync(0xffffffffu, p2, s);
    }
    const float inv = 1.f / 4096.f;
    float a0 = p0 * inv, a1 = p1 * inv, a2 = p2 * inv;
    a0 = a0 > 0.f ? a0 : NEG * a0;
    a1 = a1 > 0.f ? a1 : NEG * a1;
    a2 = a2 > 0.f ? a2 : NEG * a2;
    float e0 = __expf(a0), e1 = __expf(a1), e2 = __expf(a2);
    den0 += e0; den1 += e1; den2 += e2;

    const float4* rw = (const float4*)g_rw1 + (size_t)et * 96 + lane;
    f4fma(acc0, f4mul(h2x4(xjh0), __ldg(rw)),      e0);
    f4fma(acc1, f4mul(h2x4(xjh1), __ldg(rw + 32)), e1);
    f4fma(acc2, f4mul(h2x4(xjh2), __ldg(rw + 64)), e2);
}

// slot load: one edge's fp16 x_j (3x LDG.64) + type; predicated
#define LOADSLOT(S, idx) do {                                                 \
    if ((idx) < end) {                                                        \
        int pp = g_edg[(idx)];                                                \
        S##et = pp >> 17;                                                     \
        const uint2* xs = (const uint2*)g_xh + (size_t)(pp & 0x1FFFF) * 96;   \
        S##u0 = __ldcg(xs + lane);                                            \
        S##u1 = __ldcg(xs + 32 + lane);                                       \
        S##u2 = __ldcg(xs + 64 + lane);                                       \
    }                                                                         \
} while (0)

#define PROCSLOT(S)                                                           \
    agg_one(xih0, xih1, xih2, S##u0, S##u1, S##u2, S##et, lane,               \
            acc0, acc1, acc2, den0, den1, den2)

// ---------------- kernel: aggregation + fused BN stats ----------------
// 128 threads = 4 warps = 4 nodes per CTA; 12500 CTAs exactly cover NN.
__global__ __launch_bounds__(128) void k_agg() {
    __shared__ float s_sum[KD];
    __shared__ float s_sumsq[KD];
    for (int i = threadIdx.x; i < KD; i += 128) { s_sum[i] = 0.f; s_sumsq[i] = 0.f; }
    __syncthreads();

    int lane = threadIdx.x & 31;
    int node = blockIdx.x * 4 + (threadIdx.x >> 5);

    const uint2* xrow = (const uint2*)g_xh + (size_t)node * 96;
    uint2 xih0 = __ldcg(xrow + lane);
    uint2 xih1 = __ldcg(xrow + 32 + lane);
    uint2 xih2 = __ldcg(xrow + 64 + lane);

    float4 acc0 = make_float4(0, 0, 0, 0);
    float4 acc1 = make_float4(0, 0, 0, 0);
    float4 acc2 = make_float4(0, 0, 0, 0);
    float den0 = 0.f, den1 = 0.f, den2 = 0.f;

    int beg = g_off[node], end = g_off[node + 1];

    uint2 au0, au1, au2; int aet;
    uint2 bu0, bu1, bu2; int bet;
    uint2 cu0, cu1, cu2; int cet;
    uint2 du0, du1, du2; int det;

    LOADSLOT(a, beg + 0);
    LOADSLOT(b, beg + 1);
    LOADSLOT(c, beg + 2);
    LOADSLOT(d, beg + 3);

    // self-loop (xj = xi) while first gathers are in flight
    agg_one(xih0, xih1, xih2, xih0, xih1, xih2, LOOP_ET, lane,
            acc0, acc1, acc2, den0, den1, den2);

    for (int e = beg; e < end; e += 4) {
        { PROCSLOT(a); LOADSLOT(a, e + 4); }
        if (e + 1 < end) { PROCSLOT(b); LOADSLOT(b, e + 5); }
        if (e + 2 < end) { PROCSLOT(c); LOADSLOT(c, e + 6); }
        if (e + 3 < end) { PROCSLOT(d); LOADSLOT(d, e + 7); }
    }

    float i0 = 1.f / (den0 + 1e-16f);
    float i1 = 1.f / (den1 + 1e-16f);
    float i2 = 1.f / (den2 + 1e-16f);
    float4 o0 = make_float4(acc0.x * i0, acc0.y * i0, acc0.z * i0, acc0.w * i0);
    float4 o1 = make_float4(acc1.x * i1, acc1.y * i1, acc1.z * i1, acc1.w * i1);
    float4 o2 = make_float4(acc2.x * i2, acc2.y * i2, acc2.z * i2, acc2.w * i2);

    float4* orow = (float4*)(g_out + (size_t)node * KD);
    orow[lane]      = o0;
    orow[32 + lane] = o1;
    orow[64 + lane] = o2;

    // fused BN stats: accumulate into shared, then one global atomic per col
    int c0 = 4 * lane;
#pragma unroll
    for (int j = 0; j < 4; j++) {
        float v0 = (&o0.x)[j], v1 = (&o1.x)[j], v2 = (&o2.x)[j];
        atomicAdd(&s_sum[c0 + j],           v0);
        atomicAdd(&s_sumsq[c0 + j],         v0 * v0);
        atomicAdd(&s_sum[128 + c0 + j],     v1);
        atomicAdd(&s_sumsq[128 + c0 + j],   v1 * v1);
        atomicAdd(&s_sum[256 + c0 + j],     v2);
        atomicAdd(&s_sumsq[256 + c0 + j],   v2 * v2);
    }
    __syncthreads();
    for (int i = threadIdx.x; i < KD; i += 128) {
        atomicAdd(&g_sum[i],   s_sum[i]);
        atomicAdd(&g_sumsq[i], s_sumsq[i]);
    }
}

// ---------------- kernel: finalize BN coefficients ----------------
__global__ void k_bnfinal(const float* __restrict__ gamma, const float* __restrict__ beta) {
    int c = threadIdx.x;
    if (c < KD) {
        float mu = g_sum[c] / (float)NN;
        float var = g_sumsq[c] / (float)NN - mu * mu;
        float a = gamma[c] * rsqrtf(var + BN_EPS);
        g_a[c] = a;
        g_b[c] = beta[c] - mu * a;
    }
}

// ---------------- kernel: normalize + tanh -> d_out ----------------
__global__ void k_apply(float* __restrict__ out) {
    int i = blockIdx.x * blockDim.x + threadIdx.x;   // float4 index
    if (i < NN * (KD / 4)) {
        int c4 = (i % (KD / 4)) * 4;
        float4 v = *(const float4*)&g_out[(size_t)i * 4];
        float4 y;
        y.x = fast_tanh(v.x * g_a[c4 + 0] + g_b[c4 + 0]);
        y.y = fast_tanh(v.y * g_a[c4 + 1] + g_b[c4 + 1]);
        y.z = fast_tanh(v.z * g_a[c4 + 2] + g_b[c4 + 2]);
        y.w = fast_tanh(v.w * g_a[c4 + 3] + g_b[c4 + 3]);
        ((float4*)out)[i] = y;
    }
}

// ---------------- launch ----------------
extern "C" void kernel_launch(void* const* d_in, const int* in_sizes, int n_in,
                              void* d_out, int out_size) {
    const float* init_embed = (const float*)d_in[0];
    const float* init_rel   = (const float*)d_in[1];
    const float* pca_w      = (const float*)d_in[2];
    const float* pca_b      = (const float*)d_in[3];
    const float* loop_rel   = (const float*)d_in[4];
    const float* rel_weight = (const float*)d_in[5];
    const float* bn_gamma   = (const float*)d_in[6];
    const float* bn_beta    = (const float*)d_in[7];
    const int*   edge_index = (const int*)d_in[8];
    const int*   edge_type  = (const int*)d_in[9];
    float* out = (float*)d_out;

    k_zero<<<(NN + 255) / 256, 256>>>();                          // idx 0
    k_hist<<<(EE + 255) / 256, 256>>>(edge_index);                // idx 1
    k_split<<<(NA_PAIRS + NB_PAIRS + NW1 + NW2 + 255) / 256, 256>>>(
        init_embed, pca_w, init_rel, loop_rel, rel_weight);       // idx 2

    dim3 gg((NN + 127) / 128, KD / 128);
    k_gemm<<<gg, 256>>>(pca_b);                                   // idx 3 <- ncu capture

    k_scanA<<<NBLK, 256>>>();                                     // idx 4
    k_scanC<<<NBLK, 256>>>();                                     // idx 5
    k_scatter<<<(EE + 255) / 256, 256>>>(edge_index, edge_type);  // idx 6

    k_agg<<<NN / 4, 128>>>();                                     // idx 7

    k_bnfinal<<<1, 384>>>(bn_gamma, bn_beta);
    k_apply<<<(NN * (KD / 4) + 255) / 256, 256>>>(out);
}